// round 3
// baseline (speedup 1.0000x reference)
#include <cuda_runtime.h>

#define SEQ   256
#define BATCH 64
#define HID   1024
#define GATES 4096
#define MTOT  (SEQ*BATCH)      // 16384

#define P2_BLOCKS 128          // 128 blocks, block b owns hidden units [8b, 8b+8)

// ---------------- device-global scratch (no allocations allowed) ----------------
__device__ float g_xproj[(size_t)MTOT * GATES];   // 256 MB
__device__ float g_h[2][BATCH * HID];             // double-buffered hidden state
__device__ float g_c[BATCH * HID];                // cell state

// =======================================================================
// init: zero h0 and c0
// =======================================================================
__global__ void init_kernel() {
    int i = blockIdx.x * blockDim.x + threadIdx.x;
    if (i < BATCH * HID) { g_h[0][i] = 0.f; g_c[i] = 0.f; }
}

// =======================================================================
// Phase 1: x_proj[m][g] = sum_h x[m][h] * W_ih[g][h] + b_ih[g] + b_hh[g]
// 64x64 tile, BK=16, 256 threads, 4x4 microtile, transposed smem tiles
// so inner fetches are LDS.128. Double-buffered, one sync per k-tile.
// =======================================================================
__global__ __launch_bounds__(256) void xproj_kernel(
    const float* __restrict__ x, const float* __restrict__ Wih,
    const float* __restrict__ bih, const float* __restrict__ bhh)
{
    __shared__ float As[2][16][68];   // [buf][kk][row]
    __shared__ float Bs[2][16][68];

    const int m0 = blockIdx.y * 64;
    const int g0 = blockIdx.x * 64;
    const int tid = threadIdx.x;
    const int ty = tid >> 4;          // 0..15 -> rows ty*4..+3
    const int tx = tid & 15;          // 0..15 -> cols tx*4..+3
    const int lr = tid >> 2;          // 0..63  loader row
    const int lc = (tid & 3) << 2;    // 0,4,8,12 loader k-offset

    const float* xp = x   + (size_t)(m0 + lr) * HID + lc;
    const float* wp = Wih + (size_t)(g0 + lr) * HID + lc;

    float acc[4][4];
#pragma unroll
    for (int r = 0; r < 4; r++)
#pragma unroll
        for (int c = 0; c < 4; c++) acc[r][c] = 0.f;

    float4 pa = *(const float4*)(xp);
    float4 pb = *(const float4*)(wp);

    for (int k0 = 0; k0 < HID; k0 += 16) {
        const int buf = (k0 >> 4) & 1;
        As[buf][lc + 0][lr] = pa.x; As[buf][lc + 1][lr] = pa.y;
        As[buf][lc + 2][lr] = pa.z; As[buf][lc + 3][lr] = pa.w;
        Bs[buf][lc + 0][lr] = pb.x; Bs[buf][lc + 1][lr] = pb.y;
        Bs[buf][lc + 2][lr] = pb.z; Bs[buf][lc + 3][lr] = pb.w;
        __syncthreads();
        if (k0 + 16 < HID) {
            pa = *(const float4*)(xp + k0 + 16);
            pb = *(const float4*)(wp + k0 + 16);
        }
#pragma unroll
        for (int kk = 0; kk < 16; kk++) {
            float4 av = *(const float4*)&As[buf][kk][ty * 4];
            float4 bv = *(const float4*)&Bs[buf][kk][tx * 4];
            float a[4] = {av.x, av.y, av.z, av.w};
            float b[4] = {bv.x, bv.y, bv.z, bv.w};
#pragma unroll
            for (int r = 0; r < 4; r++)
#pragma unroll
                for (int c = 0; c < 4; c++) acc[r][c] += a[r] * b[c];
        }
        __syncthreads();   // protect buffer reuse 2 iters later is implicit; keep safe
    }

    float bs4[4];
#pragma unroll
    for (int c = 0; c < 4; c++) {
        int g = g0 + tx * 4 + c;
        bs4[c] = __ldg(&bih[g]) + __ldg(&bhh[g]);
    }
#pragma unroll
    for (int r = 0; r < 4; r++) {
        int m = m0 + ty * 4 + r;
        float4 o;
        o.x = acc[r][0] + bs4[0];
        o.y = acc[r][1] + bs4[1];
        o.z = acc[r][2] + bs4[2];
        o.w = acc[r][3] + bs4[3];
        *(float4*)&g_xproj[(size_t)m * GATES + g0 + tx * 4] = o;
    }
}

// =======================================================================
// Phase 2: one kernel per timestep (graph-captured 256x). 128 blocks x 256
// threads. Block b computes the 64x32 gate tile for its 8 hidden units
// (cols = gate gi*8+u, gi=0..3, u=0..7). K=1024 split across two
// 128-thread groups (4x4 microtiles over 16x8 threads); W and h tiles
// streamed through double-buffered smem; partials combined in smem;
// then the LSTM nonlinearity + state update.
// =======================================================================
__global__ __launch_bounds__(256) void step_kernel(
    const float* __restrict__ Whh, const float* __restrict__ xrow,
    const float* __restrict__ hin, float* __restrict__ hout,
    float* __restrict__ cst, int last, float* __restrict__ out)
{
    __shared__ float Ws[4][16][36];   // [grp*2+buf][kk][col]
    __shared__ float Hs[4][16][68];   // [grp*2+buf][kk][row]
    __shared__ float Gs[64 * 33];     // combined gate tile

    const int tid = threadIdx.x;
    const int j0  = blockIdx.x * 8;
    const int grp = tid >> 7;          // 0/1: K halves
    const int lt  = tid & 127;
    const int ty  = lt >> 3;           // 0..15 -> batch rows ty*4..+3
    const int tx  = lt & 7;            // 0..7  -> cols tx*4..+3
    const int kbase = grp * 512;

    // h loader: thread loads 2 float4 of one batch row per 16-k chunk
    const int l_row = lt >> 1;                  // 0..63
    const int l_k0  = ((2 * lt) & 3) << 2;      // 0 or 8
    const int l_k1  = ((2 * lt + 1) & 3) << 2;  // 4 or 12
    // W loader: thread loads 1 float4 along K of one weight row
    const int wc = lt >> 2;                     // 0..31 tile col
    const int wk = (lt & 3) << 2;               // 0,4,8,12
    const float* wptr = Whh + (size_t)((wc >> 3) * HID + j0 + (wc & 7)) * HID
                        + kbase + wk;
    const float* hrow = hin + l_row * HID + kbase;

    float acc[4][4];
#pragma unroll
    for (int r = 0; r < 4; r++)
#pragma unroll
        for (int c = 0; c < 4; c++) acc[r][c] = 0.f;

    float4 p0 = __ldcg((const float4*)(hrow + l_k0));
    float4 p1 = __ldcg((const float4*)(hrow + l_k1));
    float4 w0 = __ldg((const float4*)(wptr));

    for (int k0 = 0; k0 < 512; k0 += 16) {
        const int gb = grp * 2 + ((k0 >> 4) & 1);
        float* hb = &Hs[gb][0][0];
        float* wb = &Ws[gb][0][0];
        hb[(l_k0 + 0) * 68 + l_row] = p0.x;
        hb[(l_k0 + 1) * 68 + l_row] = p0.y;
        hb[(l_k0 + 2) * 68 + l_row] = p0.z;
        hb[(l_k0 + 3) * 68 + l_row] = p0.w;
        hb[(l_k1 + 0) * 68 + l_row] = p1.x;
        hb[(l_k1 + 1) * 68 + l_row] = p1.y;
        hb[(l_k1 + 2) * 68 + l_row] = p1.z;
        hb[(l_k1 + 3) * 68 + l_row] = p1.w;
        wb[(wk + 0) * 36 + wc] = w0.x;
        wb[(wk + 1) * 36 + wc] = w0.y;
        wb[(wk + 2) * 36 + wc] = w0.z;
        wb[(wk + 3) * 36 + wc] = w0.w;
        __syncthreads();
        if (k0 + 16 < 512) {
            p0 = __ldcg((const float4*)(hrow + k0 + 16 + l_k0));
            p1 = __ldcg((const float4*)(hrow + k0 + 16 + l_k1));
            w0 = __ldg((const float4*)(wptr + k0 + 16));
        }
#pragma unroll
        for (int kk = 0; kk < 16; kk++) {
            float4 av = *(const float4*)&hb[kk * 68 + ty * 4];
            float4 bv = *(const float4*)&wb[kk * 36 + tx * 4];
            float a[4] = {av.x, av.y, av.z, av.w};
            float b[4] = {bv.x, bv.y, bv.z, bv.w};
#pragma unroll
            for (int r = 0; r < 4; r++)
#pragma unroll
                for (int c = 0; c < 4; c++) acc[r][c] += a[r] * b[c];
        }
        // next iteration writes the other buffer (double-buffered, no 2nd sync)
    }

    // ---- combine the two K-half partials ----
    if (grp == 0) {
#pragma unroll
        for (int r = 0; r < 4; r++)
#pragma unroll
            for (int c = 0; c < 4; c++)
                Gs[(ty * 4 + r) * 33 + tx * 4 + c] = acc[r][c];
    }
    __syncthreads();
    if (grp == 1) {
#pragma unroll
        for (int r = 0; r < 4; r++)
#pragma unroll
            for (int c = 0; c < 4; c++)
                Gs[(ty * 4 + r) * 33 + tx * 4 + c] += acc[r][c];
    }
    __syncthreads();

    // ---- gating / state update: 512 (batch,unit) pairs, 2 per thread ----
#pragma unroll
    for (int p = 0; p < 2; p++) {
        const int pid = tid * 2 + p;
        const int b = pid >> 3, u = pid & 7;
        const float* xb = xrow + (size_t)b * GATES + j0 + u;
        float iv = Gs[b * 33 +      u] + xb[0];
        float fv = Gs[b * 33 +  8 + u] + xb[1024];
        float gv = Gs[b * 33 + 16 + u] + xb[2048];
        float ov = Gs[b * 33 + 24 + u] + xb[3072];
        float ig = 1.f / (1.f + __expf(-iv));
        float fg = 1.f / (1.f + __expf(-fv));
        float og = 1.f / (1.f + __expf(-ov));
        float gt = tanhf(gv);
        const int gidx = b * HID + j0 + u;
        float cn = fg * cst[gidx] + ig * gt;
        cst[gidx] = cn;
        float hn = og * tanhf(cn);
        hout[gidx] = hn;
        if (last) out[gidx] = hn;
    }
}

// =======================================================================
extern "C" void kernel_launch(void* const* d_in, const int* in_sizes, int n_in,
                              void* d_out, int out_size)
{
    const float* x   = (const float*)d_in[0];
    const float* Wih = (const float*)d_in[1];
    const float* Whh = (const float*)d_in[2];
    const float* bih = (const float*)d_in[3];
    const float* bhh = (const float*)d_in[4];
    float* out = (float*)d_out;
    (void)in_sizes; (void)n_in; (void)out_size;

    float* xproj_base; float* h_base; float* c_base;
    cudaGetSymbolAddress((void**)&xproj_base, g_xproj);
    cudaGetSymbolAddress((void**)&h_base,     g_h);
    cudaGetSymbolAddress((void**)&c_base,     g_c);

    init_kernel<<<(BATCH * HID + 255) / 256, 256>>>();

    dim3 g1(GATES / 64, MTOT / 64);   // (64, 256) = 16384 blocks
    xproj_kernel<<<g1, 256>>>(x, Wih, bih, bhh);

    for (int t = 0; t < SEQ; t++) {
        const float* xrow = xproj_base + (size_t)t * BATCH * GATES;
        const float* hin  = h_base + (t & 1) * (BATCH * HID);
        float*       hout = h_base + ((t + 1) & 1) * (BATCH * HID);
        step_kernel<<<P2_BLOCKS, 256>>>(Whh, xrow, hin, hout, c_base,
                                        t == SEQ - 1 ? 1 : 0, out);
    }
}

// round 5
// speedup vs baseline: 1.2508x; 1.2508x over previous
#include <cuda_runtime.h>

#define SEQ   256
#define BATCH 64
#define HID   1024
#define GATES 4096
#define MTOT  (SEQ*BATCH)      // 16384

#define P2_BLOCKS 128          // block b owns hidden units [8b, 8b+8) -> 32 gate cols

// ---------------- device-global scratch (no allocations allowed) ----------------
__device__ float g_xproj[(size_t)MTOT * GATES];   // 256 MB
__device__ float g_h[2][BATCH * HID];             // double-buffered hidden state
__device__ float g_c[BATCH * HID];                // cell state

// =======================================================================
__global__ void init_kernel() {
    int i = blockIdx.x * blockDim.x + threadIdx.x;
    if (i < BATCH * HID) { g_h[0][i] = 0.f; g_c[i] = 0.f; }
}

// =======================================================================
// Phase 1 (unchanged, proven): 64x64 tile SGEMM, 4x4 microtile,
// transposed smem tiles so inner fetches are LDS.128.
// =======================================================================
__global__ __launch_bounds__(256) void xproj_kernel(
    const float* __restrict__ x, const float* __restrict__ Wih,
    const float* __restrict__ bih, const float* __restrict__ bhh)
{
    __shared__ float As[2][16][68];
    __shared__ float Bs[2][16][68];

    const int m0 = blockIdx.y * 64;
    const int g0 = blockIdx.x * 64;
    const int tid = threadIdx.x;
    const int ty = tid >> 4;
    const int tx = tid & 15;
    const int lr = tid >> 2;
    const int lc = (tid & 3) << 2;

    const float* xp = x   + (size_t)(m0 + lr) * HID + lc;
    const float* wp = Wih + (size_t)(g0 + lr) * HID + lc;

    float acc[4][4];
#pragma unroll
    for (int r = 0; r < 4; r++)
#pragma unroll
        for (int c = 0; c < 4; c++) acc[r][c] = 0.f;

    float4 pa = *(const float4*)(xp);
    float4 pb = *(const float4*)(wp);

    for (int k0 = 0; k0 < HID; k0 += 16) {
        const int buf = (k0 >> 4) & 1;
        As[buf][lc + 0][lr] = pa.x; As[buf][lc + 1][lr] = pa.y;
        As[buf][lc + 2][lr] = pa.z; As[buf][lc + 3][lr] = pa.w;
        Bs[buf][lc + 0][lr] = pb.x; Bs[buf][lc + 1][lr] = pb.y;
        Bs[buf][lc + 2][lr] = pb.z; Bs[buf][lc + 3][lr] = pb.w;
        __syncthreads();
        if (k0 + 16 < HID) {
            pa = *(const float4*)(xp + k0 + 16);
            pb = *(const float4*)(wp + k0 + 16);
        }
#pragma unroll
        for (int kk = 0; kk < 16; kk++) {
            float4 av = *(const float4*)&As[buf][kk][ty * 4];
            float4 bv = *(const float4*)&Bs[buf][kk][tx * 4];
            float a[4] = {av.x, av.y, av.z, av.w};
            float b[4] = {bv.x, bv.y, bv.z, bv.w};
#pragma unroll
            for (int r = 0; r < 4; r++)
#pragma unroll
                for (int c = 0; c < 4; c++) acc[r][c] += a[r] * b[c];
        }
        __syncthreads();
    }

    float bs4[4];
#pragma unroll
    for (int c = 0; c < 4; c++) {
        int g = g0 + tx * 4 + c;
        bs4[c] = __ldg(&bih[g]) + __ldg(&bhh[g]);
    }
#pragma unroll
    for (int r = 0; r < 4; r++) {
        int m = m0 + ty * 4 + r;
        float4 o;
        o.x = acc[r][0] + bs4[0];
        o.y = acc[r][1] + bs4[1];
        o.z = acc[r][2] + bs4[2];
        o.w = acc[r][3] + bs4[3];
        *(float4*)&g_xproj[(size_t)m * GATES + g0 + tx * 4] = o;
    }
}

// =======================================================================
// Phase 2: per-step kernel. 128 blocks x 256 threads (8 warps).
// Each warp = one K-slice of 128 with warp-private double-buffered smem
// tiles -> NO block-wide barriers in the main loop. 8x8 microtile as
// 2x2 blocks of 4x4 (conflict-free LDS.128). Partials to transposed
// smem (stride 68 -> conflict-free reduce), one __syncthreads, 8-way
// reduce + fused LSTM gating.
// =======================================================================

// dynamic smem: Hs[8][2][8][68] + Ws[8][2][8][36] + Gt[8][32][68]
#define HS_FL   (8 * 2 * 8 * 68)     // 8704 floats
#define WS_FL   (8 * 2 * 8 * 36)     // 4608 floats
#define GT_FL   (8 * 32 * 68)        // 17408 floats
#define P2_SMEM_BYTES ((HS_FL + WS_FL + GT_FL) * 4)   // 122880 B

__global__ __launch_bounds__(256, 1) void step_kernel(
    const float* __restrict__ Whh, const float* __restrict__ xrow,
    const float* __restrict__ hin, float* __restrict__ hout,
    float* __restrict__ cst, int last, float* __restrict__ out)
{
    extern __shared__ float sm[];
    float* Hs = sm;                 // [slice][buf][k(8)][row(68)]
    float* Ws = Hs + HS_FL;         // [slice][buf][k(8)][col(36)]
    float* Gt = Ws + WS_FL;         // [slice][col(32)][row(68)] partials

    const int tid = threadIdx.x;
    const int j0  = blockIdx.x * 8;
    const int s   = tid >> 5;          // warp = K-slice, K in [s*128, s*128+128)
    const int st  = tid & 31;
    const int sy  = st >> 2;           // 0..7 -> rows sy*4 and 32+sy*4
    const int sx  = st & 3;            // 0..3 -> cols sx*4 and 16+sx*4

    float* hb0 = Hs + (s * 2) * (8 * 68);
    float* wb0 = Ws + (s * 2) * (8 * 36);

    // loader lane mapping (shared by h and w loaders)
    const int lhalf = st >> 1;         // 0..15
    const int lkf4  = (st & 1) * 4;    // 0 or 4 (k offset within 8-k chunk)

    // h: 4 float4 per lane per chunk: rows q*16+lhalf, k = chunk*8 + lkf4
    const float* hptr = hin + (size_t)lhalf * HID + s * 128 + lkf4;
    // w: 2 float4 per lane per chunk: tile cols q*16+lhalf
    const float* wptr0 = Whh + (size_t)((((0 * 16 + lhalf) >> 3) * HID) + j0 + ((0 * 16 + lhalf) & 7)) * HID + s * 128 + lkf4;
    const float* wptr1 = Whh + (size_t)((((1 * 16 + lhalf) >> 3) * HID) + j0 + ((1 * 16 + lhalf) & 7)) * HID + s * 128 + lkf4;

    float acc[8][8];
#pragma unroll
    for (int r = 0; r < 8; r++)
#pragma unroll
        for (int c = 0; c < 8; c++) acc[r][c] = 0.f;

    // prefetch chunk 0
    float4 hp[4], wp[2];
#pragma unroll
    for (int q = 0; q < 4; q++)
        hp[q] = *(const float4*)(hptr + (size_t)q * 16 * HID);
    wp[0] = *(const float4*)(wptr0);
    wp[1] = *(const float4*)(wptr1);

    for (int c0 = 0; c0 < 16; c0++) {
        const int buf = c0 & 1;
        float* hb = hb0 + buf * (8 * 68);
        float* wb = wb0 + buf * (8 * 36);
        // store transposed: [k][row] / [k][col]
#pragma unroll
        for (int q = 0; q < 4; q++) {
            const int row = q * 16 + lhalf;
            hb[(lkf4 + 0) * 68 + row] = hp[q].x;
            hb[(lkf4 + 1) * 68 + row] = hp[q].y;
            hb[(lkf4 + 2) * 68 + row] = hp[q].z;
            hb[(lkf4 + 3) * 68 + row] = hp[q].w;
        }
#pragma unroll
        for (int q = 0; q < 2; q++) {
            const int col = q * 16 + lhalf;
            wb[(lkf4 + 0) * 36 + col] = wp[q].x;
            wb[(lkf4 + 1) * 36 + col] = wp[q].y;
            wb[(lkf4 + 2) * 36 + col] = wp[q].z;
            wb[(lkf4 + 3) * 36 + col] = wp[q].w;
        }
        __syncwarp();
        if (c0 < 15) {
            const int kn = (c0 + 1) * 8;
#pragma unroll
            for (int q = 0; q < 4; q++)
                hp[q] = *(const float4*)(hptr + (size_t)q * 16 * HID + kn);
            wp[0] = *(const float4*)(wptr0 + kn);
            wp[1] = *(const float4*)(wptr1 + kn);
        }
#pragma unroll
        for (int kk = 0; kk < 8; kk++) {
            float4 a0 = *(const float4*)&hb[kk * 68 + sy * 4];
            float4 a1 = *(const float4*)&hb[kk * 68 + 32 + sy * 4];
            float4 b0 = *(const float4*)&wb[kk * 36 + sx * 4];
            float4 b1 = *(const float4*)&wb[kk * 36 + 16 + sx * 4];
            float a[8] = {a0.x, a0.y, a0.z, a0.w, a1.x, a1.y, a1.z, a1.w};
            float b[8] = {b0.x, b0.y, b0.z, b0.w, b1.x, b1.y, b1.z, b1.w};
#pragma unroll
            for (int r = 0; r < 8; r++)
#pragma unroll
                for (int c = 0; c < 8; c++) acc[r][c] += a[r] * b[c];
        }
        __syncwarp();   // reads of buf complete before it is rewritten (c0+2)
    }

    // ---- write partials transposed: Gt[s][col][row] ----
    float* gt = Gt + s * (32 * 68);
#pragma unroll
    for (int rb = 0; rb < 2; rb++)
#pragma unroll
        for (int i = 0; i < 4; i++) {
            const int row = rb * 32 + sy * 4 + i;
#pragma unroll
            for (int cb = 0; cb < 2; cb++)
#pragma unroll
                for (int j = 0; j < 4; j++) {
                    const int col = cb * 16 + sx * 4 + j;
                    gt[col * 68 + row] = acc[rb * 4 + i][cb * 4 + j];
                }
        }
    __syncthreads();

    // ---- 8-way reduce + LSTM gating: 512 (batch,unit) pairs ----
#pragma unroll
    for (int p = 0; p < 2; p++) {
        const int pid = tid + p * 256;
        const int b = pid >> 3, u = pid & 7;
        float gate[4];
#pragma unroll
        for (int gi = 0; gi < 4; gi++) {
            float v = 0.f;
#pragma unroll
            for (int ss = 0; ss < 8; ss++)
                v += Gt[ss * (32 * 68) + (gi * 8 + u) * 68 + b];
            gate[gi] = v;
        }
        const float* xb = xrow + (size_t)b * GATES + j0 + u;
        float iv = gate[0] + xb[0];
        float fv = gate[1] + xb[1024];
        float gv = gate[2] + xb[2048];
        float ov = gate[3] + xb[3072];
        float ig = 1.f / (1.f + __expf(-iv));
        float fg = 1.f / (1.f + __expf(-fv));
        float og = 1.f / (1.f + __expf(-ov));
        float gt2 = tanhf(gv);
        const int gidx = b * HID + j0 + u;
        float cn = fg * cst[gidx] + ig * gt2;
        cst[gidx] = cn;
        float hn = og * tanhf(cn);
        hout[gidx] = hn;
        if (last) out[gidx] = hn;
    }
}

// =======================================================================
extern "C" void kernel_launch(void* const* d_in, const int* in_sizes, int n_in,
                              void* d_out, int out_size)
{
    const float* x   = (const float*)d_in[0];
    const float* Wih = (const float*)d_in[1];
    const float* Whh = (const float*)d_in[2];
    const float* bih = (const float*)d_in[3];
    const float* bhh = (const float*)d_in[4];
    float* out = (float*)d_out;
    (void)in_sizes; (void)n_in; (void)out_size;

    float* xproj_base; float* h_base; float* c_base;
    cudaGetSymbolAddress((void**)&xproj_base, g_xproj);
    cudaGetSymbolAddress((void**)&h_base,     g_h);
    cudaGetSymbolAddress((void**)&c_base,     g_c);

    cudaFuncSetAttribute(step_kernel,
                         cudaFuncAttributeMaxDynamicSharedMemorySize,
                         P2_SMEM_BYTES);

    init_kernel<<<(BATCH * HID + 255) / 256, 256>>>();

    dim3 g1(GATES / 64, MTOT / 64);
    xproj_kernel<<<g1, 256>>>(x, Wih, bih, bhh);

    for (int t = 0; t < SEQ; t++) {
        const float* xrow = xproj_base + (size_t)t * BATCH * GATES;
        const float* hin  = h_base + (t & 1) * (BATCH * HID);
        float*       hout = h_base + ((t + 1) & 1) * (BATCH * HID);
        step_kernel<<<P2_BLOCKS, 256, P2_SMEM_BYTES>>>(
            Whh, xrow, hin, hout, c_base, t == SEQ - 1 ? 1 : 0, out);
    }
}

// round 9
// speedup vs baseline: 1.8975x; 1.5171x over previous
#include <cuda_runtime.h>
#include <cuda_bf16.h>
#include <stdint.h>

#define SEQ   256
#define BATCH 64
#define HID   1024
#define GATES 4096
#define MTOT  (SEQ*BATCH)      // 16384

// ---------------- device-global scratch ----------------
__device__ float g_xproj[(size_t)GATES * MTOT];                      // [gate][m]
alignas(128) __device__ __nv_bfloat16 g_Aih[(size_t)32*2*16*8192];   // [gt][pass][ch]
alignas(128) __device__ __nv_bfloat16 g_Ahh[(size_t)64*2*16*4096];   // [cta][pass][ch]
alignas(128) __device__ __nv_bfloat16 g_Axt[(size_t)128*2*16*8192];  // [mt][pass][ch]
alignas(128) __device__ __nv_bfloat16 g_hb[2*2*16*4096];             // [par][pass][ch]
__device__ float g_c[64 * 64 * 16];                                  // [cta][b][u]

// ---------------- PTX helpers (sm_100-safe: no tcgen05) ----------------
__device__ __forceinline__ uint32_t smem_u32(const void* p) {
    uint32_t a;
    asm("{ .reg .u64 t; cvta.to.shared.u64 t, %1; cvt.u32.u64 %0, t; }" : "=r"(a) : "l"(p));
    return a;
}
__device__ __forceinline__ uint32_t elect_one() {
    uint32_t p;
    asm volatile("{ .reg .pred p; elect.sync _|p, 0xFFFFFFFF; selp.b32 %0, 1, 0, p; }" : "=r"(p));
    return p;
}
__device__ __forceinline__ void mbar_init(uint32_t a, uint32_t cnt) {
    asm volatile("mbarrier.init.shared.b64 [%0], %1;" :: "r"(a), "r"(cnt) : "memory");
}
__device__ __forceinline__ void mbar_expect_tx(uint32_t a, uint32_t bytes) {
    asm volatile("mbarrier.arrive.expect_tx.shared.b64 _, [%0], %1;" :: "r"(a), "r"(bytes) : "memory");
}
__device__ __forceinline__ void mbar_arrive(uint32_t a) {
    asm volatile("mbarrier.arrive.shared.b64 _, [%0];" :: "r"(a) : "memory");
}
__device__ __forceinline__ void mbar_wait(uint32_t a, uint32_t parity) {
    asm volatile(
        "{\n\t.reg .pred P;\n\t"
        "W%=:\n\t"
        "mbarrier.try_wait.parity.acquire.cta.shared::cta.b64 P, [%0], %1, 0x989680;\n\t"
        "@P bra.uni D%=;\n\t"
        "bra.uni W%=;\n\t"
        "D%=:\n\t}"
        :: "r"(a), "r"(parity) : "memory");
}
__device__ __forceinline__ void bulk_g2s(uint32_t dst, const void* src, uint32_t bytes, uint32_t mbar) {
    asm volatile(
        "cp.async.bulk.shared::cluster.global.mbarrier::complete_tx::bytes [%0], [%1], %2, [%3];"
        :: "r"(dst), "l"(src), "r"(bytes), "r"(mbar) : "memory");
}
#define FENCE_ASYNC() asm volatile("fence.proxy.async.shared::cta;" ::: "memory")

__device__ __forceinline__ void lds128(uint32_t* r, uint32_t a) {
    asm volatile("ld.shared.v4.b32 {%0,%1,%2,%3}, [%4];"
                 : "=r"(r[0]), "=r"(r[1]), "=r"(r[2]), "=r"(r[3]) : "r"(a));
}
__device__ __forceinline__ void lds64(uint32_t* r, uint32_t a) {
    asm volatile("ld.shared.v2.b32 {%0,%1}, [%2];"
                 : "=r"(r[0]), "=r"(r[1]) : "r"(a));
}
__device__ __forceinline__ void mma16816(float* c, const uint32_t* a, const uint32_t* b) {
    asm volatile(
        "mma.sync.aligned.m16n8k16.row.col.f32.bf16.bf16.f32 "
        "{%0,%1,%2,%3}, {%4,%5,%6,%7}, {%8,%9}, {%0,%1,%2,%3};"
        : "+f"(c[0]), "+f"(c[1]), "+f"(c[2]), "+f"(c[3])
        : "r"(a[0]), "r"(a[1]), "r"(a[2]), "r"(a[3]), "r"(b[0]), "r"(b[1]));
}

// =======================================================================
__global__ void init_kernel() {
    int i = blockIdx.x * blockDim.x + threadIdx.x;
    if (i < 2 * 2 * 16 * 4096) g_hb[i] = __nv_bfloat16(0.f);
    if (i < 64 * 64 * 16) g_c[i] = 0.f;
}

// A frag layout: lane=(rm&7)*4+((k>>1)&3); slot=(k&1)+2*((rm>>3)&1)+4*((k>>3)&1)
__global__ void prep_wih(const float* __restrict__ W) {
    int idx = blockIdx.x * blockDim.x + threadIdx.x;
    int g = idx >> 10, k = idx & 1023;
    float v = W[idx];
    __nv_bfloat16 hi = __float2bfloat16(v);
    __nv_bfloat16 lo = __float2bfloat16(v - __bfloat162float(hi));
    int gt = g >> 7, m = g & 127, m16 = m >> 4, rm = m & 15;
    int ch = k >> 6, s = (k >> 4) & 3;
    int lane = (rm & 7) * 4 + ((k >> 1) & 3);
    int slot = (k & 1) + 2 * ((rm >> 3) & 1) + 4 * ((k >> 3) & 1);
    int elem = ((s * 8 + m16) * 32 + lane) * 8 + slot;
    g_Aih[((size_t)(gt * 2 + 0) * 16 + ch) * 8192 + elem] = hi;
    g_Aih[((size_t)(gt * 2 + 1) * 16 + ch) * 8192 + elem] = lo;
}

__global__ void prep_whh(const float* __restrict__ W) {
    int idx = blockIdx.x * blockDim.x + threadIdx.x;
    int g = idx >> 10, k = idx & 1023;
    float v = W[idx];
    __nv_bfloat16 hi = __float2bfloat16(v);
    __nv_bfloat16 lo = __float2bfloat16(v - __bfloat162float(hi));
    int gi = g >> 10, j = g & 1023, cta = j >> 4, ul = j & 15;
    int ch = k >> 6, s = (k >> 4) & 3;
    int lane = (ul & 7) * 4 + ((k >> 1) & 3);
    int slot = (k & 1) + 2 * ((ul >> 3) & 1) + 4 * ((k >> 3) & 1);
    int elem = ((s * 4 + gi) * 32 + lane) * 8 + slot;
    g_Ahh[((size_t)(cta * 2 + 0) * 16 + ch) * 4096 + elem] = hi;
    g_Ahh[((size_t)(cta * 2 + 1) * 16 + ch) * 4096 + elem] = lo;
}

// B frag layout: lane=(n&7)*4+((k>>1)&3); slot=(k&1)+2*((k>>3)&1)
__global__ void prep_x(const float* __restrict__ x) {
    size_t idx = (size_t)blockIdx.x * blockDim.x + threadIdx.x;
    int mm = (int)(idx >> 10), k = (int)(idx & 1023);
    float v = x[idx];
    __nv_bfloat16 hi = __float2bfloat16(v);
    __nv_bfloat16 lo = __float2bfloat16(v - __bfloat162float(hi));
    int mt = mm >> 7, n = mm & 127, n8 = n >> 3;
    int ch = k >> 6, s = (k >> 4) & 3;
    int lane = (n & 7) * 4 + ((k >> 1) & 3);
    int slot = (k & 1) + 2 * ((k >> 3) & 1);
    int elem = ((s * 16 + n8) * 32 + lane) * 4 + slot;
    g_Axt[((size_t)(mt * 2 + 0) * 16 + ch) * 8192 + elem] = hi;
    g_Axt[((size_t)(mt * 2 + 1) * 16 + ch) * 8192 + elem] = lo;
}

// =======================================================================
// xproj: M=128 gates x N=128 m per CTA, K=1024 x 3 passes. grid (32,128).
// 288 threads: warps 0-7 compute (wm 0..1 x wn 0..3), warp 8 produces.
// =======================================================================
#define XS 3
#define X_SMEM (1024 + XS * 32768)
__global__ __launch_bounds__(288, 1) void xproj_tc(
    const float* __restrict__ bih, const float* __restrict__ bhh)
{
    extern __shared__ char smc[];
    uint32_t sb = smem_u32(smc);
    const int tid = threadIdx.x, wid = tid >> 5, lane = tid & 31;
    const int gt = blockIdx.x, mt = blockIdx.y;

    uint32_t full[XS], empty[XS];
    for (int s = 0; s < XS; s++) { full[s] = sb + 8 * s; empty[s] = sb + 64 + 8 * s; }
    if (tid == 0)
        for (int s = 0; s < XS; s++) { mbar_init(full[s], 1); mbar_init(empty[s], 8); }
    FENCE_ASYNC();
    __syncthreads();

    const __nv_bfloat16* Ab = g_Aih + (size_t)gt * 2 * 16 * 8192;
    const __nv_bfloat16* Bb = g_Axt + (size_t)mt * 2 * 16 * 8192;
    const int paA[3] = {0, 0, 1}, paB[3] = {0, 1, 0};

    if (wid == 8) {
        for (int i = 0; i < 48; i++) {
            int s = i % XS, p = i / 16, c = i % 16;
            if (i >= XS) mbar_wait(empty[s], ((i / XS) - 1) & 1);
            if (elect_one()) {
                mbar_expect_tx(full[s], 32768);
                bulk_g2s(sb + 1024 + s * 32768,
                         Ab + ((size_t)paA[p] * 16 + c) * 8192, 16384, full[s]);
                bulk_g2s(sb + 1024 + s * 32768 + 16384,
                         Bb + ((size_t)paB[p] * 16 + c) * 8192, 16384, full[s]);
            }
        }
        return;
    }

    const int wm = wid >> 2, wn = wid & 3;
    float acc[4][4][4];
#pragma unroll
    for (int i = 0; i < 4; i++)
#pragma unroll
        for (int j = 0; j < 4; j++)
#pragma unroll
            for (int q = 0; q < 4; q++) acc[i][j][q] = 0.f;

    for (int i = 0; i < 48; i++) {
        int s = i % XS;
        mbar_wait(full[s], (i / XS) & 1);
        uint32_t cA = sb + 1024 + s * 32768;
        uint32_t cB = cA + 16384;
#pragma unroll
        for (int s4 = 0; s4 < 4; s4++) {
            uint32_t a[4][4], b[4][2];
#pragma unroll
            for (int i4 = 0; i4 < 4; i4++)
                lds128(a[i4], cA + ((s4 * 8 + wm * 4 + i4) * 32 + lane) * 16);
#pragma unroll
            for (int j = 0; j < 4; j++)
                lds64(b[j], cB + ((s4 * 16 + wn * 4 + j) * 32 + lane) * 8);
#pragma unroll
            for (int i4 = 0; i4 < 4; i4++)
#pragma unroll
                for (int j = 0; j < 4; j++)
                    mma16816(acc[i4][j], a[i4], b[j]);
        }
        if (elect_one()) mbar_arrive(empty[s]);
    }

    const int r = lane >> 2, c2 = (lane & 3) * 2;
#pragma unroll
    for (int i4 = 0; i4 < 4; i4++) {
        int g0 = gt * 128 + (wm * 4 + i4) * 16 + r;
        float b0 = __ldg(&bih[g0]) + __ldg(&bhh[g0]);
        float b1 = __ldg(&bih[g0 + 8]) + __ldg(&bhh[g0 + 8]);
#pragma unroll
        for (int j = 0; j < 4; j++) {
            int m = mt * 128 + wn * 32 + j * 8 + c2;
            *(float2*)&g_xproj[(size_t)g0 * MTOT + m] =
                make_float2(acc[i4][j][0] + b0, acc[i4][j][1] + b0);
            *(float2*)&g_xproj[(size_t)(g0 + 8) * MTOT + m] =
                make_float2(acc[i4][j][2] + b1, acc[i4][j][3] + b1);
        }
    }
}

// =======================================================================
// step: CTA = 16 units (M=64 gate-interleaved) x N=64 batch. 64 CTAs.
// =======================================================================
#define SS 4
#define EP_OFF (1024 + SS * 16384)
#define S_SMEM (EP_OFF + 64 * 66 * 4)
__global__ __launch_bounds__(288, 1) void step_tc(
    const float* __restrict__ xcol, int par, int last, float* __restrict__ out)
{
    extern __shared__ char smc[];
    uint32_t sb = smem_u32(smc);
    float* ep = (float*)(smc + EP_OFF);    // [64][66]
    const int tid = threadIdx.x, wid = tid >> 5, lane = tid & 31;
    const int cta = blockIdx.x;

    uint32_t full[SS], empty[SS];
    for (int s = 0; s < SS; s++) { full[s] = sb + 8 * s; empty[s] = sb + 64 + 8 * s; }
    if (tid == 0)
        for (int s = 0; s < SS; s++) { mbar_init(full[s], 1); mbar_init(empty[s], 8); }
    FENCE_ASYNC();
    __syncthreads();

    const __nv_bfloat16* Ab = g_Ahh + (size_t)cta * 2 * 16 * 4096;
    const __nv_bfloat16* Bb = g_hb + (size_t)par * 2 * 16 * 4096;
    const int paA[3] = {0, 0, 1}, paB[3] = {0, 1, 0};

    if (wid == 8) {
        for (int i = 0; i < 48; i++) {
            int s = i % SS, p = i / 16, c = i % 16;
            if (i >= SS) mbar_wait(empty[s], ((i / SS) - 1) & 1);
            if (elect_one()) {
                mbar_expect_tx(full[s], 16384);
                bulk_g2s(sb + 1024 + s * 16384,
                         Ab + ((size_t)paA[p] * 16 + c) * 4096, 8192, full[s]);
                bulk_g2s(sb + 1024 + s * 16384 + 8192,
                         Bb + ((size_t)paB[p] * 16 + c) * 4096, 8192, full[s]);
            }
        }
    } else {
        const int wm = wid >> 1, wn = wid & 1;
        float acc[4][4];
#pragma unroll
        for (int j = 0; j < 4; j++)
#pragma unroll
            for (int q = 0; q < 4; q++) acc[j][q] = 0.f;

        for (int i = 0; i < 48; i++) {
            int s = i % SS;
            mbar_wait(full[s], (i / SS) & 1);
            uint32_t cA = sb + 1024 + s * 16384;
            uint32_t cB = cA + 8192;
#pragma unroll
            for (int s4 = 0; s4 < 4; s4++) {
                uint32_t a[4], b[4][2];
                lds128(a, cA + ((s4 * 4 + wm) * 32 + lane) * 16);
#pragma unroll
                for (int j = 0; j < 4; j++)
                    lds64(b[j], cB + ((s4 * 8 + wn * 4 + j) * 32 + lane) * 8);
#pragma unroll
                for (int j = 0; j < 4; j++)
                    mma16816(acc[j], a, b[j]);
            }
            if (elect_one()) mbar_arrive(empty[s]);
        }

        const int r = lane >> 2, c2 = (lane & 3) * 2;
#pragma unroll
        for (int j = 0; j < 4; j++) {
            int b = wn * 32 + j * 8 + c2;
            int m0 = wm * 16 + r;
            *(float2*)&ep[m0 * 66 + b] = make_float2(acc[j][0], acc[j][1]);
            *(float2*)&ep[(m0 + 8) * 66 + b] = make_float2(acc[j][2], acc[j][3]);
        }
    }
    __syncthreads();

    if (tid < 256) {
#pragma unroll
        for (int p = 0; p < 4; p++) {
            const int pid = tid * 4 + p;
            const int u = pid & 15, b = pid >> 4;
            const int jg = cta * 16 + u;
            float iv = ep[(0 * 16 + u) * 66 + b] + xcol[(size_t)(0 * 1024 + jg) * MTOT + b];
            float fv = ep[(1 * 16 + u) * 66 + b] + xcol[(size_t)(1 * 1024 + jg) * MTOT + b];
            float gv = ep[(2 * 16 + u) * 66 + b] + xcol[(size_t)(2 * 1024 + jg) * MTOT + b];
            float ov = ep[(3 * 16 + u) * 66 + b] + xcol[(size_t)(3 * 1024 + jg) * MTOT + b];
            float ig = 1.f / (1.f + __expf(-iv));
            float fg = 1.f / (1.f + __expf(-fv));
            float og = 1.f / (1.f + __expf(-ov));
            float gtv = tanhf(gv);
            const int ci = cta * 1024 + b * 16 + u;
            float cn = fg * g_c[ci] + ig * gtv;
            g_c[ci] = cn;
            float hn = og * tanhf(cn);
            __nv_bfloat16 hi = __float2bfloat16(hn);
            __nv_bfloat16 lo = __float2bfloat16(hn - __bfloat162float(hi));
            const int k = jg;
            const int ch = k >> 6, s4 = (k >> 4) & 3, n8 = b >> 3;
            const int bl = (b & 7) * 4 + ((k >> 1) & 3);
            const int sl = (k & 1) + 2 * ((k >> 3) & 1);
            const int elem = ((s4 * 8 + n8) * 32 + bl) * 4 + sl;
            const int parout = par ^ 1;
            g_hb[((size_t)(parout * 2 + 0) * 16 + ch) * 4096 + elem] = hi;
            g_hb[((size_t)(parout * 2 + 1) * 16 + ch) * 4096 + elem] = lo;
            if (last) out[b * HID + jg] = hn;
        }
    }
}

// =======================================================================
extern "C" void kernel_launch(void* const* d_in, const int* in_sizes, int n_in,
                              void* d_out, int out_size)
{
    const float* x   = (const float*)d_in[0];
    const float* Wih = (const float*)d_in[1];
    const float* Whh = (const float*)d_in[2];
    const float* bih = (const float*)d_in[3];
    const float* bhh = (const float*)d_in[4];
    float* out = (float*)d_out;
    (void)in_sizes; (void)n_in; (void)out_size;

    float* xproj_base;
    cudaGetSymbolAddress((void**)&xproj_base, g_xproj);

    cudaFuncSetAttribute(xproj_tc, cudaFuncAttributeMaxDynamicSharedMemorySize, X_SMEM);
    cudaFuncSetAttribute(step_tc,  cudaFuncAttributeMaxDynamicSharedMemorySize, S_SMEM);

    init_kernel<<<(2 * 2 * 16 * 4096 + 255) / 256, 256>>>();
    prep_wih<<<(GATES * HID) / 256, 256>>>(Wih);
    prep_whh<<<(GATES * HID) / 256, 256>>>(Whh);
    prep_x<<<(int)(((size_t)MTOT * HID) / 256), 256>>>(x);

    dim3 gx(32, 128);
    xproj_tc<<<gx, 288, X_SMEM>>>(bih, bhh);

    for (int t = 0; t < SEQ; t++) {
        // xproj is [gate][m]; column base for this timestep is m = t*64
        step_tc<<<64, 288, S_SMEM>>>(xproj_base + (size_t)t * BATCH,
                                     t & 1, t == SEQ - 1 ? 1 : 0, out);
    }
}

// round 10
// speedup vs baseline: 3.3435x; 1.7620x over previous
#include <cuda_runtime.h>
#include <cuda_bf16.h>
#include <stdint.h>

#define SEQ   256
#define BATCH 64
#define HID   1024
#define GATES 4096
#define MTOT  (SEQ*BATCH)      // 16384

// ---------------- device-global scratch ----------------
__device__ float g_xproj[(size_t)GATES * MTOT];                      // [gate][m]
alignas(128) __device__ __nv_bfloat16 g_Aih[(size_t)32*2*16*8192];   // xproj A tiles
alignas(128) __device__ __nv_bfloat16 g_Ahh[(size_t)128*65536];      // Whh: per-cta 128KB frag tiles
alignas(128) __device__ __nv_bfloat16 g_Axt[(size_t)128*2*16*8192];  // xproj B tiles
alignas(128) __device__ __nv_bfloat16 g_hb[2*2*16*4096];             // h frags [par][pass][ch]
__device__ unsigned g_bar_count;
__device__ unsigned g_bar_gen;

// ---------------- PTX helpers (sm_100-safe) ----------------
__device__ __forceinline__ uint32_t smem_u32(const void* p) {
    uint32_t a;
    asm("{ .reg .u64 t; cvta.to.shared.u64 t, %1; cvt.u32.u64 %0, t; }" : "=r"(a) : "l"(p));
    return a;
}
__device__ __forceinline__ uint32_t elect_one() {
    uint32_t p;
    asm volatile("{ .reg .pred p; elect.sync _|p, 0xFFFFFFFF; selp.b32 %0, 1, 0, p; }" : "=r"(p));
    return p;
}
__device__ __forceinline__ void mbar_init(uint32_t a, uint32_t cnt) {
    asm volatile("mbarrier.init.shared.b64 [%0], %1;" :: "r"(a), "r"(cnt) : "memory");
}
__device__ __forceinline__ void mbar_expect_tx(uint32_t a, uint32_t bytes) {
    asm volatile("mbarrier.arrive.expect_tx.shared.b64 _, [%0], %1;" :: "r"(a), "r"(bytes) : "memory");
}
__device__ __forceinline__ void mbar_arrive(uint32_t a) {
    asm volatile("mbarrier.arrive.shared.b64 _, [%0];" :: "r"(a) : "memory");
}
__device__ __forceinline__ void mbar_wait(uint32_t a, uint32_t parity) {
    asm volatile(
        "{\n\t.reg .pred P;\n\t"
        "W%=:\n\t"
        "mbarrier.try_wait.parity.acquire.cta.shared::cta.b64 P, [%0], %1, 0x989680;\n\t"
        "@P bra.uni D%=;\n\t"
        "bra.uni W%=;\n\t"
        "D%=:\n\t}"
        :: "r"(a), "r"(parity) : "memory");
}
__device__ __forceinline__ void bulk_g2s(uint32_t dst, const void* src, uint32_t bytes, uint32_t mbar) {
    asm volatile(
        "cp.async.bulk.shared::cluster.global.mbarrier::complete_tx::bytes [%0], [%1], %2, [%3];"
        :: "r"(dst), "l"(src), "r"(bytes), "r"(mbar) : "memory");
}
#define FENCE_ASYNC() asm volatile("fence.proxy.async.shared::cta;" ::: "memory")

__device__ __forceinline__ void lds128(uint32_t* r, uint32_t a) {
    asm volatile("ld.shared.v4.b32 {%0,%1,%2,%3}, [%4];"
                 : "=r"(r[0]), "=r"(r[1]), "=r"(r[2]), "=r"(r[3]) : "r"(a));
}
__device__ __forceinline__ void lds64(uint32_t* r, uint32_t a) {
    asm volatile("ld.shared.v2.b32 {%0,%1}, [%2];"
                 : "=r"(r[0]), "=r"(r[1]) : "r"(a));
}
__device__ __forceinline__ void mma16816(float* c, const uint32_t* a, const uint32_t* b) {
    asm volatile(
        "mma.sync.aligned.m16n8k16.row.col.f32.bf16.bf16.f32 "
        "{%0,%1,%2,%3}, {%4,%5,%6,%7}, {%8,%9}, {%0,%1,%2,%3};"
        : "+f"(c[0]), "+f"(c[1]), "+f"(c[2]), "+f"(c[3])
        : "r"(a[0]), "r"(a[1]), "r"(a[2]), "r"(a[3]), "r"(b[0]), "r"(b[1]));
}

// =======================================================================
__global__ void init_kernel() {
    int i = blockIdx.x * blockDim.x + threadIdx.x;
    if (i < 2 * 2 * 16 * 4096) g_hb[i] = __nv_bfloat16(0.f);
}

// A frag layout: lane=(rm&7)*4+((k>>1)&3); slot=(k&1)+2*((rm>>3)&1)+4*((k>>3)&1)
__global__ void prep_wih(const float* __restrict__ W) {
    int idx = blockIdx.x * blockDim.x + threadIdx.x;
    int g = idx >> 10, k = idx & 1023;
    float v = W[idx];
    __nv_bfloat16 hi = __float2bfloat16(v);
    __nv_bfloat16 lo = __float2bfloat16(v - __bfloat162float(hi));
    int gt = g >> 7, m = g & 127, m16 = m >> 4, rm = m & 15;
    int ch = k >> 6, s = (k >> 4) & 3;
    int lane = (rm & 7) * 4 + ((k >> 1) & 3);
    int slot = (k & 1) + 2 * ((rm >> 3) & 1) + 4 * ((k >> 3) & 1);
    int elem = ((s * 8 + m16) * 32 + lane) * 8 + slot;
    g_Aih[((size_t)(gt * 2 + 0) * 16 + ch) * 8192 + elem] = hi;
    g_Aih[((size_t)(gt * 2 + 1) * 16 + ch) * 8192 + elem] = lo;
}

// Whh for persistent kernel: cta owns units [cta*8, cta*8+8); row m = gi*8+u
// per-cta layout elem = ((((p*16+ch)*2+mt2)*4+s)*32+lane)*8+slot
__global__ void prep_whh(const float* __restrict__ W) {
    int idx = blockIdx.x * blockDim.x + threadIdx.x;
    int g = idx >> 10, k = idx & 1023;
    float v = W[idx];
    __nv_bfloat16 hi = __float2bfloat16(v);
    __nv_bfloat16 lo = __float2bfloat16(v - __bfloat162float(hi));
    int gi = g >> 10, j = g & 1023, cta = j >> 3, u = j & 7;
    int m = gi * 8 + u, mt2 = m >> 4, rm = m & 15;
    int ch = k >> 6, s = (k >> 4) & 3;
    int lane = (rm & 7) * 4 + ((k >> 1) & 3);
    int slot = (k & 1) + 2 * ((rm >> 3) & 1) + 4 * ((k >> 3) & 1);
    int e0 = ((((0 * 16 + ch) * 2 + mt2) * 4 + s) * 32 + lane) * 8 + slot;
    int e1 = ((((1 * 16 + ch) * 2 + mt2) * 4 + s) * 32 + lane) * 8 + slot;
    g_Ahh[(size_t)cta * 65536 + e0] = hi;
    g_Ahh[(size_t)cta * 65536 + e1] = lo;
}

// B frag layout: lane=(n&7)*4+((k>>1)&3); slot=(k&1)+2*((k>>3)&1)
__global__ void prep_x(const float* __restrict__ x) {
    size_t idx = (size_t)blockIdx.x * blockDim.x + threadIdx.x;
    int mm = (int)(idx >> 10), k = (int)(idx & 1023);
    float v = x[idx];
    __nv_bfloat16 hi = __float2bfloat16(v);
    __nv_bfloat16 lo = __float2bfloat16(v - __bfloat162float(hi));
    int mt = mm >> 7, n = mm & 127, n8 = n >> 3;
    int ch = k >> 6, s = (k >> 4) & 3;
    int lane = (n & 7) * 4 + ((k >> 1) & 3);
    int slot = (k & 1) + 2 * ((k >> 3) & 1);
    int elem = ((s * 16 + n8) * 32 + lane) * 4 + slot;
    g_Axt[((size_t)(mt * 2 + 0) * 16 + ch) * 8192 + elem] = hi;
    g_Axt[((size_t)(mt * 2 + 1) * 16 + ch) * 8192 + elem] = lo;
}

// =======================================================================
// xproj (unchanged, proven): M=128 gates x N=128 m per CTA. grid (32,128).
// =======================================================================
#define XS 3
#define X_SMEM (1024 + XS * 32768)
__global__ __launch_bounds__(288, 1) void xproj_tc(
    const float* __restrict__ bih, const float* __restrict__ bhh)
{
    extern __shared__ char smc[];
    uint32_t sb = smem_u32(smc);
    const int tid = threadIdx.x, wid = tid >> 5, lane = tid & 31;
    const int gt = blockIdx.x, mt = blockIdx.y;

    uint32_t full[XS], empty[XS];
    for (int s = 0; s < XS; s++) { full[s] = sb + 8 * s; empty[s] = sb + 64 + 8 * s; }
    if (tid == 0)
        for (int s = 0; s < XS; s++) { mbar_init(full[s], 1); mbar_init(empty[s], 8); }
    FENCE_ASYNC();
    __syncthreads();

    const __nv_bfloat16* Ab = g_Aih + (size_t)gt * 2 * 16 * 8192;
    const __nv_bfloat16* Bb = g_Axt + (size_t)mt * 2 * 16 * 8192;
    const int paA[3] = {0, 0, 1}, paB[3] = {0, 1, 0};

    if (wid == 8) {
        for (int i = 0; i < 48; i++) {
            int s = i % XS, p = i / 16, c = i % 16;
            if (i >= XS) mbar_wait(empty[s], ((i / XS) - 1) & 1);
            if (elect_one()) {
                mbar_expect_tx(full[s], 32768);
                bulk_g2s(sb + 1024 + s * 32768,
                         Ab + ((size_t)paA[p] * 16 + c) * 8192, 16384, full[s]);
                bulk_g2s(sb + 1024 + s * 32768 + 16384,
                         Bb + ((size_t)paB[p] * 16 + c) * 8192, 16384, full[s]);
            }
        }
        return;
    }

    const int wm = wid >> 2, wn = wid & 3;
    float acc[4][4][4];
#pragma unroll
    for (int i = 0; i < 4; i++)
#pragma unroll
        for (int j = 0; j < 4; j++)
#pragma unroll
            for (int q = 0; q < 4; q++) acc[i][j][q] = 0.f;

    for (int i = 0; i < 48; i++) {
        int s = i % XS;
        mbar_wait(full[s], (i / XS) & 1);
        uint32_t cA = sb + 1024 + s * 32768;
        uint32_t cB = cA + 16384;
#pragma unroll
        for (int s4 = 0; s4 < 4; s4++) {
            uint32_t a[4][4], b[4][2];
#pragma unroll
            for (int i4 = 0; i4 < 4; i4++)
                lds128(a[i4], cA + ((s4 * 8 + wm * 4 + i4) * 32 + lane) * 16);
#pragma unroll
            for (int j = 0; j < 4; j++)
                lds64(b[j], cB + ((s4 * 16 + wn * 4 + j) * 32 + lane) * 8);
#pragma unroll
            for (int i4 = 0; i4 < 4; i4++)
#pragma unroll
                for (int j = 0; j < 4; j++)
                    mma16816(acc[i4][j], a[i4], b[j]);
        }
        if (elect_one()) mbar_arrive(empty[s]);
    }

    const int r = lane >> 2, c2 = (lane & 3) * 2;
#pragma unroll
    for (int i4 = 0; i4 < 4; i4++) {
        int g0 = gt * 128 + (wm * 4 + i4) * 16 + r;
        float b0 = __ldg(&bih[g0]) + __ldg(&bhh[g0]);
        float b1 = __ldg(&bih[g0 + 8]) + __ldg(&bhh[g0 + 8]);
#pragma unroll
        for (int j = 0; j < 4; j++) {
            int m = mt * 128 + wn * 32 + j * 8 + c2;
            *(float2*)&g_xproj[(size_t)g0 * MTOT + m] =
                make_float2(acc[i4][j][0] + b0, acc[i4][j][1] + b0);
            *(float2*)&g_xproj[(size_t)(g0 + 8) * MTOT + m] =
                make_float2(acc[i4][j][2] + b1, acc[i4][j][3] + b1);
        }
    }
}

// =======================================================================
// Persistent LSTM recurrence: 128 CTAs x 256 threads, one launch.
// CTA owns 8 units (M=32 rows); warp w owns K-slice [128w,128w+128).
// Whh slice resident in smem; h frags read via __ldcg; partials -> smem
// -> 8-way reduce + gating; cell state in registers; grid barrier/step.
// =======================================================================
#define A_OFF   1024
#define PT_OFF  (A_OFF + 131072)
#define P_SMEM  (PT_OFF + 8 * 2112 * 4)     // 1024+131072+67584 = 199680

__device__ __forceinline__ void grid_barrier_128() {
    __syncthreads();
    if (threadIdx.x == 0) {
        __threadfence();
        unsigned g = *((volatile unsigned*)&g_bar_gen);
        if (atomicAdd(&g_bar_count, 1u) == 127u) {
            atomicExch(&g_bar_count, 0u);
            __threadfence();
            atomicAdd(&g_bar_gen, 1u);
        } else {
            while (*((volatile unsigned*)&g_bar_gen) == g) { __nanosleep(64); }
        }
        __threadfence();
    }
    __syncthreads();
}

__global__ __launch_bounds__(256, 1) void lstm_persist(float* __restrict__ out)
{
    extern __shared__ char smc[];
    uint32_t sb = smem_u32(smc);
    const uint32_t As = sb + A_OFF;
    float* Pt = (float*)(smc + PT_OFF);     // [8][32][66]
    const int tid = threadIdx.x, wid = tid >> 5, lane = tid & 31;
    const int cta = blockIdx.x;

    // load resident Whh slice (128KB, layout identical to gmem)
    {
        const float4* src = (const float4*)(g_Ahh + (size_t)cta * 65536);
        float4* dst = (float4*)(smc + A_OFF);
        for (int i = tid; i < 8192; i += 256) dst[i] = __ldg(&src[i]);
    }
    __syncthreads();

    const int r = lane >> 2, c2 = (lane & 3) * 2;
    const int gb = tid & 63;                 // gating batch
    const int gu = tid >> 6;                 // gating unit group (0..3)
    float cst[2] = {0.f, 0.f};               // cell state, units gu*2+{0,1}
    int par = 0;

    for (int t = 0; t < SEQ; t++) {
        float acc[2][8][4];
#pragma unroll
        for (int i = 0; i < 2; i++)
#pragma unroll
            for (int j = 0; j < 8; j++)
#pragma unroll
                for (int q = 0; q < 4; q++) acc[i][j][q] = 0.f;

#pragma unroll
        for (int cc = 0; cc < 2; cc++) {
            const int ch = wid * 2 + cc;
            uint32_t ah[2][4][4], al[2][4][4];
#pragma unroll
            for (int mt2 = 0; mt2 < 2; mt2++)
#pragma unroll
                for (int s = 0; s < 4; s++) {
                    lds128(ah[mt2][s], As + ((((0 * 16 + ch) * 2 + mt2) * 4 + s) << 9) + lane * 16);
                    lds128(al[mt2][s], As + ((((1 * 16 + ch) * 2 + mt2) * 4 + s) << 9) + lane * 16);
                }
            const char* bh_base = (const char*)g_hb + ((size_t)((par * 2 + 0) * 16 + ch)) * 8192;
            const char* bl_base = (const char*)g_hb + ((size_t)((par * 2 + 1) * 16 + ch)) * 8192;
#pragma unroll
            for (int n8 = 0; n8 < 8; n8++) {
                uint32_t b[4][2];
#pragma unroll
                for (int s = 0; s < 4; s++) {
                    uint2 v = __ldcg((const uint2*)(bh_base + (s * 8 + n8) * 256 + lane * 8));
                    b[s][0] = v.x; b[s][1] = v.y;
                }
#pragma unroll
                for (int mt2 = 0; mt2 < 2; mt2++)
#pragma unroll
                    for (int s = 0; s < 4; s++) {
                        mma16816(acc[mt2][n8], ah[mt2][s], b[s]);
                        mma16816(acc[mt2][n8], al[mt2][s], b[s]);
                    }
            }
#pragma unroll
            for (int n8 = 0; n8 < 8; n8++) {
                uint32_t b[4][2];
#pragma unroll
                for (int s = 0; s < 4; s++) {
                    uint2 v = __ldcg((const uint2*)(bl_base + (s * 8 + n8) * 256 + lane * 8));
                    b[s][0] = v.x; b[s][1] = v.y;
                }
#pragma unroll
                for (int mt2 = 0; mt2 < 2; mt2++)
#pragma unroll
                    for (int s = 0; s < 4; s++)
                        mma16816(acc[mt2][n8], ah[mt2][s], b[s]);
            }
        }

        // write partials Pt[wid][m][b]
#pragma unroll
        for (int mt2 = 0; mt2 < 2; mt2++)
#pragma unroll
            for (int n8 = 0; n8 < 8; n8++) {
                *(float2*)&Pt[wid * 2112 + (mt2 * 16 + r) * 66 + n8 * 8 + c2] =
                    make_float2(acc[mt2][n8][0], acc[mt2][n8][1]);
                *(float2*)&Pt[wid * 2112 + (mt2 * 16 + r + 8) * 66 + n8 * 8 + c2] =
                    make_float2(acc[mt2][n8][2], acc[mt2][n8][3]);
            }
        __syncthreads();

        // gating: thread handles units gu*2+{0,1}, batch gb
        const int parout = par ^ 1;
#pragma unroll
        for (int p2 = 0; p2 < 2; p2++) {
            const int u = gu * 2 + p2;
            const int jg = cta * 8 + u;
            float gate[4];
#pragma unroll
            for (int gi = 0; gi < 4; gi++) {
                const int m = gi * 8 + u;
                float v = 0.f;
#pragma unroll
                for (int w = 0; w < 8; w++) v += Pt[w * 2112 + m * 66 + gb];
                gate[gi] = v + __ldg(&g_xproj[(size_t)(gi * 1024 + jg) * MTOT + t * 64 + gb]);
            }
            float ig = 1.f / (1.f + __expf(-gate[0]));
            float fg = 1.f / (1.f + __expf(-gate[1]));
            float gtv = tanhf(gate[2]);
            float og = 1.f / (1.f + __expf(-gate[3]));
            float cn = fg * cst[p2] + ig * gtv;
            cst[p2] = cn;
            float hn = og * tanhf(cn);
            __nv_bfloat16 hi = __float2bfloat16(hn);
            __nv_bfloat16 lo = __float2bfloat16(hn - __bfloat162float(hi));
            const int k = jg;
            const int ch = k >> 6, s4 = (k >> 4) & 3, n8 = gb >> 3;
            const int bl2 = (gb & 7) * 4 + ((k >> 1) & 3);
            const int sl = (k & 1) + 2 * ((k >> 3) & 1);
            const int elem = ((s4 * 8 + n8) * 32 + bl2) * 4 + sl;
            g_hb[((size_t)(parout * 2 + 0) * 16 + ch) * 4096 + elem] = hi;
            g_hb[((size_t)(parout * 2 + 1) * 16 + ch) * 4096 + elem] = lo;
            if (t == SEQ - 1) out[gb * HID + jg] = hn;
        }

        grid_barrier_128();
        par ^= 1;
    }
}

// =======================================================================
extern "C" void kernel_launch(void* const* d_in, const int* in_sizes, int n_in,
                              void* d_out, int out_size)
{
    const float* x   = (const float*)d_in[0];
    const float* Wih = (const float*)d_in[1];
    const float* Whh = (const float*)d_in[2];
    const float* bih = (const float*)d_in[3];
    const float* bhh = (const float*)d_in[4];
    float* out = (float*)d_out;
    (void)in_sizes; (void)n_in; (void)out_size;

    cudaFuncSetAttribute(xproj_tc, cudaFuncAttributeMaxDynamicSharedMemorySize, X_SMEM);
    cudaFuncSetAttribute(lstm_persist, cudaFuncAttributeMaxDynamicSharedMemorySize, P_SMEM);

    init_kernel<<<(2 * 2 * 16 * 4096 + 255) / 256, 256>>>();
    prep_wih<<<(GATES * HID) / 256, 256>>>(Wih);
    prep_whh<<<(GATES * HID) / 256, 256>>>(Whh);
    prep_x<<<(int)(((size_t)MTOT * HID) / 256), 256>>>(x);

    dim3 gx(32, 128);
    xproj_tc<<<gx, 288, X_SMEM>>>(bih, bhh);

    lstm_persist<<<128, 256, P_SMEM>>>(out);
}

// round 12
// speedup vs baseline: 3.5083x; 1.0493x over previous
#include <cuda_runtime.h>
#include <cuda_bf16.h>
#include <stdint.h>

#define SEQ   256
#define BATCH 64
#define HID   1024
#define GATES 4096
#define MTOT  (SEQ*BATCH)      // 16384

// ---------------- device-global scratch ----------------
__device__ float g_xproj[(size_t)GATES * MTOT];                      // [gate][m]
alignas(128) __device__ __nv_bfloat16 g_Aih[(size_t)32*2*16*8192];   // xproj A tiles
alignas(128) __device__ __nv_bfloat16 g_Ahh[(size_t)128*65536];      // Whh per-cta 128KB
alignas(128) __device__ __nv_bfloat16 g_Axt[(size_t)128*2*16*8192];  // xproj B tiles (packed)
alignas(128) __device__ __nv_bfloat16 g_hb[2*2*16*4096];             // h frags (packed)
__device__ unsigned g_bar_count;
__device__ unsigned g_bar_gen;

// ---------------- PTX helpers (sm_100-safe) ----------------
__device__ __forceinline__ uint32_t smem_u32(const void* p) {
    uint32_t a;
    asm("{ .reg .u64 t; cvta.to.shared.u64 t, %1; cvt.u32.u64 %0, t; }" : "=r"(a) : "l"(p));
    return a;
}
__device__ __forceinline__ uint32_t elect_one() {
    uint32_t p;
    asm volatile("{ .reg .pred p; elect.sync _|p, 0xFFFFFFFF; selp.b32 %0, 1, 0, p; }" : "=r"(p));
    return p;
}
__device__ __forceinline__ void mbar_init(uint32_t a, uint32_t cnt) {
    asm volatile("mbarrier.init.shared.b64 [%0], %1;" :: "r"(a), "r"(cnt) : "memory");
}
__device__ __forceinline__ void mbar_expect_tx(uint32_t a, uint32_t bytes) {
    asm volatile("mbarrier.arrive.expect_tx.shared.b64 _, [%0], %1;" :: "r"(a), "r"(bytes) : "memory");
}
__device__ __forceinline__ void mbar_arrive(uint32_t a) {
    asm volatile("mbarrier.arrive.shared.b64 _, [%0];" :: "r"(a) : "memory");
}
__device__ __forceinline__ void mbar_wait(uint32_t a, uint32_t parity) {
    asm volatile(
        "{\n\t.reg .pred P;\n\t"
        "W%=:\n\t"
        "mbarrier.try_wait.parity.acquire.cta.shared::cta.b64 P, [%0], %1, 0x989680;\n\t"
        "@P bra.uni D%=;\n\t"
        "bra.uni W%=;\n\t"
        "D%=:\n\t}"
        :: "r"(a), "r"(parity) : "memory");
}
__device__ __forceinline__ void bulk_g2s(uint32_t dst, const void* src, uint32_t bytes, uint32_t mbar) {
    asm volatile(
        "cp.async.bulk.shared::cluster.global.mbarrier::complete_tx::bytes [%0], [%1], %2, [%3];"
        :: "r"(dst), "l"(src), "r"(bytes), "r"(mbar) : "memory");
}
#define FENCE_ASYNC() asm volatile("fence.proxy.async.shared::cta;" ::: "memory")

__device__ __forceinline__ void lds128(uint32_t* r, uint32_t a) {
    asm volatile("ld.shared.v4.b32 {%0,%1,%2,%3}, [%4];"
                 : "=r"(r[0]), "=r"(r[1]), "=r"(r[2]), "=r"(r[3]) : "r"(a));
}
__device__ __forceinline__ void mma16816(float* c, const uint32_t* a, const uint32_t* b) {
    asm volatile(
        "mma.sync.aligned.m16n8k16.row.col.f32.bf16.bf16.f32 "
        "{%0,%1,%2,%3}, {%4,%5,%6,%7}, {%8,%9}, {%0,%1,%2,%3};"
        : "+f"(c[0]), "+f"(c[1]), "+f"(c[2]), "+f"(c[3])
        : "r"(a[0]), "r"(a[1]), "r"(a[2]), "r"(a[3]), "r"(b[0]), "r"(b[1]));
}

// =======================================================================
// prep_all: one kernel does hb-zero + Wih + Whh + x fragment prep.
//   blocks [0,1024): zero g_hb
//   blocks [1024, 17408): Wih
//   blocks [17408, 33792): Whh
//   blocks [33792, 99328): x
// =======================================================================
__global__ __launch_bounds__(256) void prep_all(
    const float* __restrict__ Wih, const float* __restrict__ Whh,
    const float* __restrict__ x)
{
    const int blk = blockIdx.x, tid = threadIdx.x;
    if (blk < 1024) {
        g_hb[blk * 256 + tid] = __nv_bfloat16(0.f);
    } else if (blk < 17408) {
        // A frag: lane=(rm&7)*4+((k>>1)&3); slot=(k&1)+2*((rm>>3)&1)+4*((k>>3)&1)
        int idx = (blk - 1024) * 256 + tid;
        int g = idx >> 10, k = idx & 1023;
        float v = Wih[idx];
        __nv_bfloat16 hi = __float2bfloat16(v);
        __nv_bfloat16 lo = __float2bfloat16(v - __bfloat162float(hi));
        int gt = g >> 7, m = g & 127, m16 = m >> 4, rm = m & 15;
        int ch = k >> 6, s = (k >> 4) & 3;
        int lane = (rm & 7) * 4 + ((k >> 1) & 3);
        int slot = (k & 1) + 2 * ((rm >> 3) & 1) + 4 * ((k >> 3) & 1);
        int elem = ((s * 8 + m16) * 32 + lane) * 8 + slot;
        g_Aih[((size_t)(gt * 2 + 0) * 16 + ch) * 8192 + elem] = hi;
        g_Aih[((size_t)(gt * 2 + 1) * 16 + ch) * 8192 + elem] = lo;
    } else if (blk < 33792) {
        int idx = (blk - 17408) * 256 + tid;
        int g = idx >> 10, k = idx & 1023;
        float v = Whh[idx];
        __nv_bfloat16 hi = __float2bfloat16(v);
        __nv_bfloat16 lo = __float2bfloat16(v - __bfloat162float(hi));
        int gi = g >> 10, j = g & 1023, cta = j >> 3, u = j & 7;
        int m = gi * 8 + u, mt2 = m >> 4, rm = m & 15;
        int ch = k >> 6, s = (k >> 4) & 3;
        int lane = (rm & 7) * 4 + ((k >> 1) & 3);
        int slot = (k & 1) + 2 * ((rm >> 3) & 1) + 4 * ((k >> 3) & 1);
        int e0 = ((((0 * 16 + ch) * 2 + mt2) * 4 + s) * 32 + lane) * 8 + slot;
        int e1 = ((((1 * 16 + ch) * 2 + mt2) * 4 + s) * 32 + lane) * 8 + slot;
        g_Ahh[(size_t)cta * 65536 + e0] = hi;
        g_Ahh[(size_t)cta * 65536 + e1] = lo;
    } else {
        // B frag PACKED: pair (n8,n8+1) in one 16B lane group
        size_t idx = (size_t)(blk - 33792) * 256 + tid;
        int mm = (int)(idx >> 10), k = (int)(idx & 1023);
        float v = x[idx];
        __nv_bfloat16 hi = __float2bfloat16(v);
        __nv_bfloat16 lo = __float2bfloat16(v - __bfloat162float(hi));
        int mt = mm >> 7, n = mm & 127, n8 = n >> 3, n8p = n8 >> 1, q = n8 & 1;
        int ch = k >> 6, s = (k >> 4) & 3;
        int lane = (n & 7) * 4 + ((k >> 1) & 3);
        int slot = (k & 1) + 2 * ((k >> 3) & 1);
        int elem = ((s * 8 + n8p) * 32 + lane) * 8 + q * 4 + slot;
        g_Axt[((size_t)(mt * 2 + 0) * 16 + ch) * 8192 + elem] = hi;
        g_Axt[((size_t)(mt * 2 + 1) * 16 + ch) * 8192 + elem] = lo;
    }
}

// =======================================================================
// xproj: M=128 gates x N=128 m per CTA. grid (32,128). 288 threads.
// Warp tile 32(M)x64(N): wm=wid>>1 (0..3), wn=wid&1. Packed-B lds128.
// 2 CTAs/SM for latency hiding.
// =======================================================================
#define XS 3
#define X_SMEM (1024 + XS * 32768)
__global__ __launch_bounds__(288, 2) void xproj_tc(
    const float* __restrict__ bih, const float* __restrict__ bhh)
{
    extern __shared__ char smc[];
    uint32_t sb = smem_u32(smc);
    const int tid = threadIdx.x, wid = tid >> 5, lane = tid & 31;
    const int gt = blockIdx.x, mt = blockIdx.y;

    uint32_t full[XS], empty[XS];
    for (int s = 0; s < XS; s++) { full[s] = sb + 8 * s; empty[s] = sb + 64 + 8 * s; }
    if (tid == 0)
        for (int s = 0; s < XS; s++) { mbar_init(full[s], 1); mbar_init(empty[s], 8); }
    FENCE_ASYNC();
    __syncthreads();

    const __nv_bfloat16* Ab = g_Aih + (size_t)gt * 2 * 16 * 8192;
    const __nv_bfloat16* Bb = g_Axt + (size_t)mt * 2 * 16 * 8192;
    const int paA[3] = {0, 0, 1}, paB[3] = {0, 1, 0};

    if (wid == 8) {
        for (int i = 0; i < 48; i++) {
            int s = i % XS, p = i / 16, c = i % 16;
            if (i >= XS) mbar_wait(empty[s], ((i / XS) - 1) & 1);
            if (elect_one()) {
                mbar_expect_tx(full[s], 32768);
                bulk_g2s(sb + 1024 + s * 32768,
                         Ab + ((size_t)paA[p] * 16 + c) * 8192, 16384, full[s]);
                bulk_g2s(sb + 1024 + s * 32768 + 16384,
                         Bb + ((size_t)paB[p] * 16 + c) * 8192, 16384, full[s]);
            }
        }
        return;
    }

    const int wm = wid >> 1, wn = wid & 1;
    float acc[2][8][4];
#pragma unroll
    for (int i = 0; i < 2; i++)
#pragma unroll
        for (int j = 0; j < 8; j++)
#pragma unroll
            for (int q = 0; q < 4; q++) acc[i][j][q] = 0.f;

    for (int i = 0; i < 48; i++) {
        int s = i % XS;
        mbar_wait(full[s], (i / XS) & 1);
        uint32_t cA = sb + 1024 + s * 32768;
        uint32_t cB = cA + 16384;
#pragma unroll
        for (int s4 = 0; s4 < 4; s4++) {
            uint32_t a[2][4], b[4][4];
#pragma unroll
            for (int i4 = 0; i4 < 2; i4++)
                lds128(a[i4], cA + ((s4 * 8 + wm * 2 + i4) * 32 + lane) * 16);
#pragma unroll
            for (int p = 0; p < 4; p++)
                lds128(b[p], cB + ((s4 * 8 + wn * 4 + p) * 32 + lane) * 16);
#pragma unroll
            for (int i4 = 0; i4 < 2; i4++)
#pragma unroll
                for (int p = 0; p < 4; p++) {
                    mma16816(acc[i4][2 * p], a[i4], &b[p][0]);
                    mma16816(acc[i4][2 * p + 1], a[i4], &b[p][2]);
                }
        }
        if (elect_one()) mbar_arrive(empty[s]);
    }

    const int r = lane >> 2, c2 = (lane & 3) * 2;
#pragma unroll
    for (int i4 = 0; i4 < 2; i4++) {
        int g0 = gt * 128 + (wm * 2 + i4) * 16 + r;
        float b0 = __ldg(&bih[g0]) + __ldg(&bhh[g0]);
        float b1 = __ldg(&bih[g0 + 8]) + __ldg(&bhh[g0 + 8]);
#pragma unroll
        for (int j = 0; j < 8; j++) {
            int m = mt * 128 + wn * 64 + j * 8 + c2;
            *(float2*)&g_xproj[(size_t)g0 * MTOT + m] =
                make_float2(acc[i4][j][0] + b0, acc[i4][j][1] + b0);
            *(float2*)&g_xproj[(size_t)(g0 + 8) * MTOT + m] =
                make_float2(acc[i4][j][2] + b1, acc[i4][j][3] + b1);
        }
    }
}

// =======================================================================
// Persistent LSTM recurrence (proven R10 structure, packed-B uint4 loads)
// =======================================================================
#define A_OFF   1024
#define PT_OFF  (A_OFF + 131072)
#define P_SMEM  (PT_OFF + 8 * 2112 * 4)

__device__ __forceinline__ void grid_barrier_128() {
    __syncthreads();
    if (threadIdx.x == 0) {
        __threadfence();
        unsigned g = *((volatile unsigned*)&g_bar_gen);
        if (atomicAdd(&g_bar_count, 1u) == 127u) {
            atomicExch(&g_bar_count, 0u);
            __threadfence();
            atomicAdd(&g_bar_gen, 1u);
        } else {
            while (*((volatile unsigned*)&g_bar_gen) == g) { __nanosleep(64); }
        }
        __threadfence();
    }
    __syncthreads();
}

__global__ __launch_bounds__(256, 1) void lstm_persist(float* __restrict__ out)
{
    extern __shared__ char smc[];
    uint32_t sb = smem_u32(smc);
    const uint32_t As = sb + A_OFF;
    float* Pt = (float*)(smc + PT_OFF);     // [8][32][66]
    const int tid = threadIdx.x, wid = tid >> 5, lane = tid & 31;
    const int cta = blockIdx.x;

    {
        const float4* src = (const float4*)(g_Ahh + (size_t)cta * 65536);
        float4* dst = (float4*)(smc + A_OFF);
        for (int i = tid; i < 8192; i += 256) dst[i] = __ldg(&src[i]);
    }
    __syncthreads();

    const int r = lane >> 2, c2 = (lane & 3) * 2;
    const int gb = tid & 63;
    const int gu = tid >> 6;
    float cst[2] = {0.f, 0.f};
    int par = 0;

    for (int t = 0; t < SEQ; t++) {
        float acc[2][8][4];
#pragma unroll
        for (int i = 0; i < 2; i++)
#pragma unroll
            for (int j = 0; j < 8; j++)
#pragma unroll
                for (int q = 0; q < 4; q++) acc[i][j][q] = 0.f;

#pragma unroll
        for (int cc = 0; cc < 2; cc++) {
            const int ch = wid * 2 + cc;
            uint32_t ah[2][4][4], al[2][4][4];
#pragma unroll
            for (int mt2 = 0; mt2 < 2; mt2++)
#pragma unroll
                for (int s = 0; s < 4; s++) {
                    lds128(ah[mt2][s], As + ((((0 * 16 + ch) * 2 + mt2) * 4 + s) << 9) + lane * 16);
                    lds128(al[mt2][s], As + ((((1 * 16 + ch) * 2 + mt2) * 4 + s) << 9) + lane * 16);
                }
            const char* bh_base = (const char*)g_hb + ((size_t)((par * 2 + 0) * 16 + ch)) * 8192;
            const char* bl_base = (const char*)g_hb + ((size_t)((par * 2 + 1) * 16 + ch)) * 8192;
            // hi pass: ah*bh + al*bh
#pragma unroll
            for (int n8p = 0; n8p < 4; n8p++) {
                uint4 v[4];
#pragma unroll
                for (int s = 0; s < 4; s++)
                    v[s] = __ldcg((const uint4*)(bh_base + ((s * 4 + n8p) * 32 + lane) * 16));
#pragma unroll
                for (int mt2 = 0; mt2 < 2; mt2++)
#pragma unroll
                    for (int s = 0; s < 4; s++) {
                        mma16816(acc[mt2][2 * n8p], ah[mt2][s], &v[s].x);
                        mma16816(acc[mt2][2 * n8p + 1], ah[mt2][s], &v[s].z);
                        mma16816(acc[mt2][2 * n8p], al[mt2][s], &v[s].x);
                        mma16816(acc[mt2][2 * n8p + 1], al[mt2][s], &v[s].z);
                    }
            }
            // lo pass: ah*bl
#pragma unroll
            for (int n8p = 0; n8p < 4; n8p++) {
                uint4 v[4];
#pragma unroll
                for (int s = 0; s < 4; s++)
                    v[s] = __ldcg((const uint4*)(bl_base + ((s * 4 + n8p) * 32 + lane) * 16));
#pragma unroll
                for (int mt2 = 0; mt2 < 2; mt2++)
#pragma unroll
                    for (int s = 0; s < 4; s++) {
                        mma16816(acc[mt2][2 * n8p], ah[mt2][s], &v[s].x);
                        mma16816(acc[mt2][2 * n8p + 1], ah[mt2][s], &v[s].z);
                    }
            }
        }

#pragma unroll
        for (int mt2 = 0; mt2 < 2; mt2++)
#pragma unroll
            for (int n8 = 0; n8 < 8; n8++) {
                *(float2*)&Pt[wid * 2112 + (mt2 * 16 + r) * 66 + n8 * 8 + c2] =
                    make_float2(acc[mt2][n8][0], acc[mt2][n8][1]);
                *(float2*)&Pt[wid * 2112 + (mt2 * 16 + r + 8) * 66 + n8 * 8 + c2] =
                    make_float2(acc[mt2][n8][2], acc[mt2][n8][3]);
            }
        __syncthreads();

        const int parout = par ^ 1;
#pragma unroll
        for (int p2 = 0; p2 < 2; p2++) {
            const int u = gu * 2 + p2;
            const int jg = cta * 8 + u;
            float gate[4];
#pragma unroll
            for (int gi = 0; gi < 4; gi++) {
                const int m = gi * 8 + u;
                float v = 0.f;
#pragma unroll
                for (int w = 0; w < 8; w++) v += Pt[w * 2112 + m * 66 + gb];
                gate[gi] = v + __ldg(&g_xproj[(size_t)(gi * 1024 + jg) * MTOT + t * 64 + gb]);
            }
            float ig = 1.f / (1.f + __expf(-gate[0]));
            float fg = 1.f / (1.f + __expf(-gate[1]));
            float gtv = tanhf(gate[2]);
            float og = 1.f / (1.f + __expf(-gate[3]));
            float cn = fg * cst[p2] + ig * gtv;
            cst[p2] = cn;
            float hn = og * tanhf(cn);
            __nv_bfloat16 hi = __float2bfloat16(hn);
            __nv_bfloat16 lo = __float2bfloat16(hn - __bfloat162float(hi));
            const int k = jg;
            const int ch = k >> 6, s4 = (k >> 4) & 3;
            const int n8p = gb >> 4, q = (gb >> 3) & 1;
            const int bl2 = (gb & 7) * 4 + ((k >> 1) & 3);
            const int sl = (k & 1) + 2 * ((k >> 3) & 1);
            const int elem = ((s4 * 4 + n8p) * 32 + bl2) * 8 + q * 4 + sl;
            g_hb[((size_t)(parout * 2 + 0) * 16 + ch) * 4096 + elem] = hi;
            g_hb[((size_t)(parout * 2 + 1) * 16 + ch) * 4096 + elem] = lo;
            if (t == SEQ - 1) out[gb * HID + jg] = hn;
        }

        grid_barrier_128();
        par ^= 1;
    }
}

// =======================================================================
extern "C" void kernel_launch(void* const* d_in, const int* in_sizes, int n_in,
                              void* d_out, int out_size)
{
    const float* x   = (const float*)d_in[0];
    const float* Wih = (const float*)d_in[1];
    const float* Whh = (const float*)d_in[2];
    const float* bih = (const float*)d_in[3];
    const float* bhh = (const float*)d_in[4];
    float* out = (float*)d_out;
    (void)in_sizes; (void)n_in; (void)out_size;

    cudaFuncSetAttribute(xproj_tc, cudaFuncAttributeMaxDynamicSharedMemorySize, X_SMEM);
    cudaFuncSetAttribute(lstm_persist, cudaFuncAttributeMaxDynamicSharedMemorySize, P_SMEM);

    prep_all<<<99328, 256>>>(Wih, Whh, x);

    dim3 gx(32, 128);
    xproj_tc<<<gx, 288, X_SMEM>>>(bih, bhh);

    lstm_persist<<<128, 256, P_SMEM>>>(out);
}

// round 13
// speedup vs baseline: 4.1908x; 1.1946x over previous
#include <cuda_runtime.h>
#include <cuda_fp16.h>
#include <stdint.h>

#define SEQ   256
#define BATCH 64
#define HID   1024
#define GATES 4096
#define MTOT  (SEQ*BATCH)      // 16384

// ---------------- device-global scratch ----------------
__device__ float g_xproj[(size_t)GATES * MTOT];                  // [gate][m]
alignas(128) __device__ __half g_Aih[(size_t)32*16*2*8192];      // Wih [gt][ch][part][8192]
alignas(128) __device__ __half g_Ahh[(size_t)128*65536];         // Whh per-cta 128KB (hi+lo)
alignas(128) __device__ __half g_Axt[(size_t)128*16*8192];       // x single fp16 [mt][ch][8192]
alignas(128) __device__ __half g_hb[2*16*4096];                  // h single fp16 [par][ch][4096]
__device__ unsigned g_bar_count;
__device__ unsigned g_bar_gen;

// ---------------- PTX helpers (sm_100-safe) ----------------
__device__ __forceinline__ uint32_t smem_u32(const void* p) {
    uint32_t a;
    asm("{ .reg .u64 t; cvta.to.shared.u64 t, %1; cvt.u32.u64 %0, t; }" : "=r"(a) : "l"(p));
    return a;
}
__device__ __forceinline__ uint32_t elect_one() {
    uint32_t p;
    asm volatile("{ .reg .pred p; elect.sync _|p, 0xFFFFFFFF; selp.b32 %0, 1, 0, p; }" : "=r"(p));
    return p;
}
__device__ __forceinline__ void mbar_init(uint32_t a, uint32_t cnt) {
    asm volatile("mbarrier.init.shared.b64 [%0], %1;" :: "r"(a), "r"(cnt) : "memory");
}
__device__ __forceinline__ void mbar_expect_tx(uint32_t a, uint32_t bytes) {
    asm volatile("mbarrier.arrive.expect_tx.shared.b64 _, [%0], %1;" :: "r"(a), "r"(bytes) : "memory");
}
__device__ __forceinline__ void mbar_arrive(uint32_t a) {
    asm volatile("mbarrier.arrive.shared.b64 _, [%0];" :: "r"(a) : "memory");
}
__device__ __forceinline__ void mbar_wait(uint32_t a, uint32_t parity) {
    asm volatile(
        "{\n\t.reg .pred P;\n\t"
        "W%=:\n\t"
        "mbarrier.try_wait.parity.acquire.cta.shared::cta.b64 P, [%0], %1, 0x989680;\n\t"
        "@P bra.uni D%=;\n\t"
        "bra.uni W%=;\n\t"
        "D%=:\n\t}"
        :: "r"(a), "r"(parity) : "memory");
}
__device__ __forceinline__ void bulk_g2s(uint32_t dst, const void* src, uint32_t bytes, uint32_t mbar) {
    asm volatile(
        "cp.async.bulk.shared::cluster.global.mbarrier::complete_tx::bytes [%0], [%1], %2, [%3];"
        :: "r"(dst), "l"(src), "r"(bytes), "r"(mbar) : "memory");
}
#define FENCE_ASYNC() asm volatile("fence.proxy.async.shared::cta;" ::: "memory")

__device__ __forceinline__ void lds128(uint32_t* r, uint32_t a) {
    asm volatile("ld.shared.v4.b32 {%0,%1,%2,%3}, [%4];"
                 : "=r"(r[0]), "=r"(r[1]), "=r"(r[2]), "=r"(r[3]) : "r"(a));
}
__device__ __forceinline__ void mma16816(float* c, const uint32_t* a, const uint32_t* b) {
    asm volatile(
        "mma.sync.aligned.m16n8k16.row.col.f32.f16.f16.f32 "
        "{%0,%1,%2,%3}, {%4,%5,%6,%7}, {%8,%9}, {%0,%1,%2,%3};"
        : "+f"(c[0]), "+f"(c[1]), "+f"(c[2]), "+f"(c[3])
        : "r"(a[0]), "r"(a[1]), "r"(a[2]), "r"(a[3]), "r"(b[0]), "r"(b[1]));
}

// =======================================================================
// prep_all: hb-zero + Wih + Whh + x fragment prep (fp16).
//   blocks [0,512): zero g_hb
//   blocks [512, 16896): Wih (hi/lo pair)
//   blocks [16896, 33280): Whh (hi/lo pair)
//   blocks [33280, 98816): x (single)
// =======================================================================
__global__ __launch_bounds__(256) void prep_all(
    const float* __restrict__ Wih, const float* __restrict__ Whh,
    const float* __restrict__ x)
{
    const int blk = blockIdx.x, tid = threadIdx.x;
    if (blk < 512) {
        g_hb[blk * 256 + tid] = __float2half(0.f);
    } else if (blk < 16896) {
        // A frag: lane=(rm&7)*4+((k>>1)&3); slot=(k&1)+2*((rm>>3)&1)+4*((k>>3)&1)
        int idx = (blk - 512) * 256 + tid;
        int g = idx >> 10, k = idx & 1023;
        float v = Wih[idx];
        __half hi = __float2half(v);
        __half lo = __float2half(v - __half2float(hi));
        int gt = g >> 7, m = g & 127, m16 = m >> 4, rm = m & 15;
        int ch = k >> 6, s = (k >> 4) & 3;
        int lane = (rm & 7) * 4 + ((k >> 1) & 3);
        int slot = (k & 1) + 2 * ((rm >> 3) & 1) + 4 * ((k >> 3) & 1);
        int elem = ((s * 8 + m16) * 32 + lane) * 8 + slot;
        g_Aih[(((size_t)gt * 16 + ch) * 2 + 0) * 8192 + elem] = hi;
        g_Aih[(((size_t)gt * 16 + ch) * 2 + 1) * 8192 + elem] = lo;
    } else if (blk < 33280) {
        int idx = (blk - 16896) * 256 + tid;
        int g = idx >> 10, k = idx & 1023;
        float v = Whh[idx];
        __half hi = __float2half(v);
        __half lo = __float2half(v - __half2float(hi));
        int gi = g >> 10, j = g & 1023, cta = j >> 3, u = j & 7;
        int m = gi * 8 + u, mt2 = m >> 4, rm = m & 15;
        int ch = k >> 6, s = (k >> 4) & 3;
        int lane = (rm & 7) * 4 + ((k >> 1) & 3);
        int slot = (k & 1) + 2 * ((rm >> 3) & 1) + 4 * ((k >> 3) & 1);
        int e0 = ((((0 * 16 + ch) * 2 + mt2) * 4 + s) * 32 + lane) * 8 + slot;
        int e1 = ((((1 * 16 + ch) * 2 + mt2) * 4 + s) * 32 + lane) * 8 + slot;
        g_Ahh[(size_t)cta * 65536 + e0] = hi;
        g_Ahh[(size_t)cta * 65536 + e1] = lo;
    } else {
        // B frag PACKED single fp16: pair (n8,n8+1) in one 16B lane group
        size_t idx = (size_t)(blk - 33280) * 256 + tid;
        int mm = (int)(idx >> 10), k = (int)(idx & 1023);
        float v = x[idx];
        int mt = mm >> 7, n = mm & 127, n8 = n >> 3, n8p = n8 >> 1, q = n8 & 1;
        int ch = k >> 6, s = (k >> 4) & 3;
        int lane = (n & 7) * 4 + ((k >> 1) & 3);
        int slot = (k & 1) + 2 * ((k >> 3) & 1);
        int elem = ((s * 8 + n8p) * 32 + lane) * 8 + q * 4 + slot;
        g_Axt[((size_t)mt * 16 + ch) * 8192 + elem] = __float2half(v);
    }
}

// =======================================================================
// xproj: M=128 gates x N=128 m per CTA. grid (32,128). 288 threads.
// 16 K-chunks; each chunk: A hi+lo (32KB) + B single (16KB); 2-pass mma.
// XS=2 double buffer, 2 CTAs/SM.
// =======================================================================
#define XS 2
#define X_SMEM (1024 + XS * 49152)
__global__ __launch_bounds__(288, 2) void xproj_tc(
    const float* __restrict__ bih, const float* __restrict__ bhh)
{
    extern __shared__ char smc[];
    uint32_t sb = smem_u32(smc);
    const int tid = threadIdx.x, wid = tid >> 5, lane = tid & 31;
    const int gt = blockIdx.x, mt = blockIdx.y;

    uint32_t full[XS], empty[XS];
    for (int s = 0; s < XS; s++) { full[s] = sb + 8 * s; empty[s] = sb + 64 + 8 * s; }
    if (tid == 0)
        for (int s = 0; s < XS; s++) { mbar_init(full[s], 1); mbar_init(empty[s], 8); }
    FENCE_ASYNC();
    __syncthreads();

    if (wid == 8) {
        for (int i = 0; i < 16; i++) {
            int s = i % XS;
            if (i >= XS) mbar_wait(empty[s], ((i / XS) - 1) & 1);
            if (elect_one()) {
                mbar_expect_tx(full[s], 49152);
                bulk_g2s(sb + 1024 + s * 49152,
                         g_Aih + ((size_t)gt * 16 + i) * 16384, 32768, full[s]);
                bulk_g2s(sb + 1024 + s * 49152 + 32768,
                         g_Axt + ((size_t)mt * 16 + i) * 8192, 16384, full[s]);
            }
        }
        return;
    }

    const int wm = wid >> 1, wn = wid & 1;
    float acc[2][8][4];
#pragma unroll
    for (int i = 0; i < 2; i++)
#pragma unroll
        for (int j = 0; j < 8; j++)
#pragma unroll
            for (int q = 0; q < 4; q++) acc[i][j][q] = 0.f;

    for (int i = 0; i < 16; i++) {
        int s = i % XS;
        mbar_wait(full[s], (i / XS) & 1);
        uint32_t cAh = sb + 1024 + s * 49152;
        uint32_t cAl = cAh + 16384;
        uint32_t cB  = cAh + 32768;
#pragma unroll
        for (int s4 = 0; s4 < 4; s4++) {
            uint32_t ah[2][4], al[2][4], b[4][4];
#pragma unroll
            for (int i4 = 0; i4 < 2; i4++) {
                lds128(ah[i4], cAh + ((s4 * 8 + wm * 2 + i4) * 32 + lane) * 16);
                lds128(al[i4], cAl + ((s4 * 8 + wm * 2 + i4) * 32 + lane) * 16);
            }
#pragma unroll
            for (int p = 0; p < 4; p++)
                lds128(b[p], cB + ((s4 * 8 + wn * 4 + p) * 32 + lane) * 16);
#pragma unroll
            for (int i4 = 0; i4 < 2; i4++)
#pragma unroll
                for (int p = 0; p < 4; p++) {
                    mma16816(acc[i4][2 * p], ah[i4], &b[p][0]);
                    mma16816(acc[i4][2 * p + 1], ah[i4], &b[p][2]);
                    mma16816(acc[i4][2 * p], al[i4], &b[p][0]);
                    mma16816(acc[i4][2 * p + 1], al[i4], &b[p][2]);
                }
        }
        if (elect_one()) mbar_arrive(empty[s]);
    }

    const int r = lane >> 2, c2 = (lane & 3) * 2;
#pragma unroll
    for (int i4 = 0; i4 < 2; i4++) {
        int g0 = gt * 128 + (wm * 2 + i4) * 16 + r;
        float b0 = __ldg(&bih[g0]) + __ldg(&bhh[g0]);
        float b1 = __ldg(&bih[g0 + 8]) + __ldg(&bhh[g0 + 8]);
#pragma unroll
        for (int j = 0; j < 8; j++) {
            int m = mt * 128 + wn * 64 + j * 8 + c2;
            *(float2*)&g_xproj[(size_t)g0 * MTOT + m] =
                make_float2(acc[i4][j][0] + b0, acc[i4][j][1] + b0);
            *(float2*)&g_xproj[(size_t)(g0 + 8) * MTOT + m] =
                make_float2(acc[i4][j][2] + b1, acc[i4][j][3] + b1);
        }
    }
}

// =======================================================================
// Persistent LSTM recurrence: fp16 2-pass, single-fp16 h broadcast.
// =======================================================================
#define A_OFF   1024
#define PT_OFF  (A_OFF + 131072)
#define P_SMEM  (PT_OFF + 8 * 2112 * 4)

__device__ __forceinline__ void grid_barrier_128() {
    __syncthreads();
    if (threadIdx.x == 0) {
        __threadfence();
        unsigned g = *((volatile unsigned*)&g_bar_gen);
        if (atomicAdd(&g_bar_count, 1u) == 127u) {
            atomicExch(&g_bar_count, 0u);
            __threadfence();
            atomicAdd(&g_bar_gen, 1u);
        } else {
            while (*((volatile unsigned*)&g_bar_gen) == g) { __nanosleep(64); }
        }
        __threadfence();
    }
    __syncthreads();
}

__global__ __launch_bounds__(256, 1) void lstm_persist(float* __restrict__ out)
{
    extern __shared__ char smc[];
    uint32_t sb = smem_u32(smc);
    const uint32_t As = sb + A_OFF;
    float* Pt = (float*)(smc + PT_OFF);     // [8][32][66]
    const int tid = threadIdx.x, wid = tid >> 5, lane = tid & 31;
    const int cta = blockIdx.x;

    {
        const float4* src = (const float4*)(g_Ahh + (size_t)cta * 65536);
        float4* dst = (float4*)(smc + A_OFF);
        for (int i = tid; i < 8192; i += 256) dst[i] = __ldg(&src[i]);
    }
    __syncthreads();

    const int r = lane >> 2, c2 = (lane & 3) * 2;
    const int gb = tid & 63;
    const int gu = tid >> 6;
    float cst[2] = {0.f, 0.f};
    int par = 0;

    for (int t = 0; t < SEQ; t++) {
        float acc[2][8][4];
#pragma unroll
        for (int i = 0; i < 2; i++)
#pragma unroll
            for (int j = 0; j < 8; j++)
#pragma unroll
                for (int q = 0; q < 4; q++) acc[i][j][q] = 0.f;

#pragma unroll
        for (int cc = 0; cc < 2; cc++) {
            const int ch = wid * 2 + cc;
            uint32_t ah[2][4][4], al[2][4][4];
#pragma unroll
            for (int mt2 = 0; mt2 < 2; mt2++)
#pragma unroll
                for (int s = 0; s < 4; s++) {
                    lds128(ah[mt2][s], As + ((((0 * 16 + ch) * 2 + mt2) * 4 + s) << 9) + lane * 16);
                    lds128(al[mt2][s], As + ((((1 * 16 + ch) * 2 + mt2) * 4 + s) << 9) + lane * 16);
                }
            const char* b_base = (const char*)g_hb + ((size_t)(par * 16 + ch)) * 8192;
#pragma unroll
            for (int n8p = 0; n8p < 4; n8p++) {
                uint4 v[4];
#pragma unroll
                for (int s = 0; s < 4; s++)
                    v[s] = __ldcg((const uint4*)(b_base + ((s * 4 + n8p) * 32 + lane) * 16));
#pragma unroll
                for (int mt2 = 0; mt2 < 2; mt2++)
#pragma unroll
                    for (int s = 0; s < 4; s++) {
                        mma16816(acc[mt2][2 * n8p], ah[mt2][s], &v[s].x);
                        mma16816(acc[mt2][2 * n8p + 1], ah[mt2][s], &v[s].z);
                        mma16816(acc[mt2][2 * n8p], al[mt2][s], &v[s].x);
                        mma16816(acc[mt2][2 * n8p + 1], al[mt2][s], &v[s].z);
                    }
            }
        }

#pragma unroll
        for (int mt2 = 0; mt2 < 2; mt2++)
#pragma unroll
            for (int n8 = 0; n8 < 8; n8++) {
                *(float2*)&Pt[wid * 2112 + (mt2 * 16 + r) * 66 + n8 * 8 + c2] =
                    make_float2(acc[mt2][n8][0], acc[mt2][n8][1]);
                *(float2*)&Pt[wid * 2112 + (mt2 * 16 + r + 8) * 66 + n8 * 8 + c2] =
                    make_float2(acc[mt2][n8][2], acc[mt2][n8][3]);
            }
        __syncthreads();

        const int parout = par ^ 1;
#pragma unroll
        for (int p2 = 0; p2 < 2; p2++) {
            const int u = gu * 2 + p2;
            const int jg = cta * 8 + u;
            float gate[4];
#pragma unroll
            for (int gi = 0; gi < 4; gi++) {
                const int m = gi * 8 + u;
                float v = 0.f;
#pragma unroll
                for (int w = 0; w < 8; w++) v += Pt[w * 2112 + m * 66 + gb];
                gate[gi] = v + __ldg(&g_xproj[(size_t)(gi * 1024 + jg) * MTOT + t * 64 + gb]);
            }
            float ig = 1.f / (1.f + __expf(-gate[0]));
            float fg = 1.f / (1.f + __expf(-gate[1]));
            float gtv = tanhf(gate[2]);
            float og = 1.f / (1.f + __expf(-gate[3]));
            float cn = fg * cst[p2] + ig * gtv;
            cst[p2] = cn;
            float hn = og * tanhf(cn);
            const int k = jg;
            const int ch = k >> 6, s4 = (k >> 4) & 3;
            const int n8p = gb >> 4, q = (gb >> 3) & 1;
            const int bl2 = (gb & 7) * 4 + ((k >> 1) & 3);
            const int sl = (k & 1) + 2 * ((k >> 3) & 1);
            const int elem = ((s4 * 4 + n8p) * 32 + bl2) * 8 + q * 4 + sl;
            g_hb[((size_t)(parout * 16 + ch)) * 4096 + elem] = __float2half(hn);
            if (t == SEQ - 1) out[gb * HID + jg] = hn;
        }

        grid_barrier_128();
        par ^= 1;
    }
}

// =======================================================================
extern "C" void kernel_launch(void* const* d_in, const int* in_sizes, int n_in,
                              void* d_out, int out_size)
{
    const float* x   = (const float*)d_in[0];
    const float* Wih = (const float*)d_in[1];
    const float* Whh = (const float*)d_in[2];
    const float* bih = (const float*)d_in[3];
    const float* bhh = (const float*)d_in[4];
    float* out = (float*)d_out;
    (void)in_sizes; (void)n_in; (void)out_size;

    cudaFuncSetAttribute(xproj_tc, cudaFuncAttributeMaxDynamicSharedMemorySize, X_SMEM);
    cudaFuncSetAttribute(lstm_persist, cudaFuncAttributeMaxDynamicSharedMemorySize, P_SMEM);

    prep_all<<<98816, 256>>>(Wih, Whh, x);

    dim3 gx(32, 128);
    xproj_tc<<<gx, 288, X_SMEM>>>(bih, bhh);

    lstm_persist<<<128, 256, P_SMEM>>>(out);
}

// round 14
// speedup vs baseline: 5.3163x; 1.2686x over previous
#include <cuda_runtime.h>
#include <cuda_fp16.h>
#include <stdint.h>

#define SEQ   256
#define BATCH 64
#define HID   1024
#define GATES 4096
#define MTOT  (SEQ*BATCH)      // 16384

// ---------------- device-global scratch ----------------
__device__ float g_xproj[(size_t)GATES * MTOT];                  // [gate][m]
alignas(128) __device__ __half g_Aih[(size_t)32*16*8192];        // Wih single fp16 [gt][ch][8192]
alignas(128) __device__ __half g_Ahh[(size_t)128*32768];         // Whh single fp16, per-cta 64KB
alignas(128) __device__ __half g_Axt[(size_t)128*16*8192];       // x single fp16 [mt][ch][8192]
alignas(128) __device__ __half g_hb[2*16*4096];                  // h single fp16 [par][ch][4096]
__device__ unsigned g_bar_count;
__device__ unsigned g_bar_gen;

// ---------------- PTX helpers (sm_100-safe) ----------------
__device__ __forceinline__ uint32_t smem_u32(const void* p) {
    uint32_t a;
    asm("{ .reg .u64 t; cvta.to.shared.u64 t, %1; cvt.u32.u64 %0, t; }" : "=r"(a) : "l"(p));
    return a;
}
__device__ __forceinline__ uint32_t elect_one() {
    uint32_t p;
    asm volatile("{ .reg .pred p; elect.sync _|p, 0xFFFFFFFF; selp.b32 %0, 1, 0, p; }" : "=r"(p));
    return p;
}
__device__ __forceinline__ void mbar_init(uint32_t a, uint32_t cnt) {
    asm volatile("mbarrier.init.shared.b64 [%0], %1;" :: "r"(a), "r"(cnt) : "memory");
}
__device__ __forceinline__ void mbar_expect_tx(uint32_t a, uint32_t bytes) {
    asm volatile("mbarrier.arrive.expect_tx.shared.b64 _, [%0], %1;" :: "r"(a), "r"(bytes) : "memory");
}
__device__ __forceinline__ void mbar_arrive(uint32_t a) {
    asm volatile("mbarrier.arrive.shared.b64 _, [%0];" :: "r"(a) : "memory");
}
__device__ __forceinline__ void mbar_wait(uint32_t a, uint32_t parity) {
    asm volatile(
        "{\n\t.reg .pred P;\n\t"
        "W%=:\n\t"
        "mbarrier.try_wait.parity.acquire.cta.shared::cta.b64 P, [%0], %1, 0x989680;\n\t"
        "@P bra.uni D%=;\n\t"
        "bra.uni W%=;\n\t"
        "D%=:\n\t}"
        :: "r"(a), "r"(parity) : "memory");
}
__device__ __forceinline__ void bulk_g2s(uint32_t dst, const void* src, uint32_t bytes, uint32_t mbar) {
    asm volatile(
        "cp.async.bulk.shared::cluster.global.mbarrier::complete_tx::bytes [%0], [%1], %2, [%3];"
        :: "r"(dst), "l"(src), "r"(bytes), "r"(mbar) : "memory");
}
#define FENCE_ASYNC() asm volatile("fence.proxy.async.shared::cta;" ::: "memory")

__device__ __forceinline__ void lds128(uint32_t* r, uint32_t a) {
    asm volatile("ld.shared.v4.b32 {%0,%1,%2,%3}, [%4];"
                 : "=r"(r[0]), "=r"(r[1]), "=r"(r[2]), "=r"(r[3]) : "r"(a));
}
__device__ __forceinline__ void mma16816(float* c, const uint32_t* a, const uint32_t* b) {
    asm volatile(
        "mma.sync.aligned.m16n8k16.row.col.f32.f16.f16.f32 "
        "{%0,%1,%2,%3}, {%4,%5,%6,%7}, {%8,%9}, {%0,%1,%2,%3};"
        : "+f"(c[0]), "+f"(c[1]), "+f"(c[2]), "+f"(c[3])
        : "r"(a[0]), "r"(a[1]), "r"(a[2]), "r"(a[3]), "r"(b[0]), "r"(b[1]));
}

// =======================================================================
// prep_all (1-pass fp16):
//   [0,512): zero g_hb
//   [512, 16896): Wih single
//   [16896, 33280): Whh single
//   [33280, 98816): x single (packed pairs)
// =======================================================================
__global__ __launch_bounds__(256) void prep_all(
    const float* __restrict__ Wih, const float* __restrict__ Whh,
    const float* __restrict__ x)
{
    const int blk = blockIdx.x, tid = threadIdx.x;
    if (blk < 512) {
        g_hb[blk * 256 + tid] = __float2half(0.f);
    } else if (blk < 16896) {
        // A frag: lane=(rm&7)*4+((k>>1)&3); slot=(k&1)+2*((rm>>3)&1)+4*((k>>3)&1)
        int idx = (blk - 512) * 256 + tid;
        int g = idx >> 10, k = idx & 1023;
        int gt = g >> 7, m = g & 127, m16 = m >> 4, rm = m & 15;
        int ch = k >> 6, s = (k >> 4) & 3;
        int lane = (rm & 7) * 4 + ((k >> 1) & 3);
        int slot = (k & 1) + 2 * ((rm >> 3) & 1) + 4 * ((k >> 3) & 1);
        int elem = ((s * 8 + m16) * 32 + lane) * 8 + slot;
        g_Aih[((size_t)gt * 16 + ch) * 8192 + elem] = __float2half(Wih[idx]);
    } else if (blk < 33280) {
        int idx = (blk - 16896) * 256 + tid;
        int g = idx >> 10, k = idx & 1023;
        int gi = g >> 10, j = g & 1023, cta = j >> 3, u = j & 7;
        int m = gi * 8 + u, mt2 = m >> 4, rm = m & 15;
        int ch = k >> 6, s = (k >> 4) & 3;
        int lane = (rm & 7) * 4 + ((k >> 1) & 3);
        int slot = (k & 1) + 2 * ((rm >> 3) & 1) + 4 * ((k >> 3) & 1);
        int elem = (((ch * 2 + mt2) * 4 + s) * 32 + lane) * 8 + slot;
        g_Ahh[(size_t)cta * 32768 + elem] = __float2half(Whh[idx]);
    } else {
        // B frag PACKED: pair (n8,n8+1) in one 16B lane group
        size_t idx = (size_t)(blk - 33280) * 256 + tid;
        int mm = (int)(idx >> 10), k = (int)(idx & 1023);
        int mt = mm >> 7, n = mm & 127, n8 = n >> 3, n8p = n8 >> 1, q = n8 & 1;
        int ch = k >> 6, s = (k >> 4) & 3;
        int lane = (n & 7) * 4 + ((k >> 1) & 3);
        int slot = (k & 1) + 2 * ((k >> 3) & 1);
        int elem = ((s * 8 + n8p) * 32 + lane) * 8 + q * 4 + slot;
        g_Axt[((size_t)mt * 16 + ch) * 8192 + elem] = __float2half(x[idx]);
    }
}

// =======================================================================
// xproj (1-pass): M=128 gates x N=128 m per CTA. grid (32,128). 288 thr.
// 16 chunks: A 16KB + B 16KB; XS=3 ring; 2 CTAs/SM.
// =======================================================================
#define XS 3
#define X_SMEM (1024 + XS * 32768)
__global__ __launch_bounds__(288, 2) void xproj_tc(
    const float* __restrict__ bih, const float* __restrict__ bhh)
{
    extern __shared__ char smc[];
    uint32_t sb = smem_u32(smc);
    const int tid = threadIdx.x, wid = tid >> 5, lane = tid & 31;
    const int gt = blockIdx.x, mt = blockIdx.y;

    uint32_t full[XS], empty[XS];
    for (int s = 0; s < XS; s++) { full[s] = sb + 8 * s; empty[s] = sb + 64 + 8 * s; }
    if (tid == 0)
        for (int s = 0; s < XS; s++) { mbar_init(full[s], 1); mbar_init(empty[s], 8); }
    FENCE_ASYNC();
    __syncthreads();

    if (wid == 8) {
        for (int i = 0; i < 16; i++) {
            int s = i % XS;
            if (i >= XS) mbar_wait(empty[s], ((i / XS) - 1) & 1);
            if (elect_one()) {
                mbar_expect_tx(full[s], 32768);
                bulk_g2s(sb + 1024 + s * 32768,
                         g_Aih + ((size_t)gt * 16 + i) * 8192, 16384, full[s]);
                bulk_g2s(sb + 1024 + s * 32768 + 16384,
                         g_Axt + ((size_t)mt * 16 + i) * 8192, 16384, full[s]);
            }
        }
        return;
    }

    const int wm = wid >> 1, wn = wid & 1;
    float acc[2][8][4];
#pragma unroll
    for (int i = 0; i < 2; i++)
#pragma unroll
        for (int j = 0; j < 8; j++)
#pragma unroll
            for (int q = 0; q < 4; q++) acc[i][j][q] = 0.f;

    for (int i = 0; i < 16; i++) {
        int s = i % XS;
        mbar_wait(full[s], (i / XS) & 1);
        uint32_t cA = sb + 1024 + s * 32768;
        uint32_t cB = cA + 16384;
#pragma unroll
        for (int s4 = 0; s4 < 4; s4++) {
            uint32_t a[2][4], b[4][4];
#pragma unroll
            for (int i4 = 0; i4 < 2; i4++)
                lds128(a[i4], cA + ((s4 * 8 + wm * 2 + i4) * 32 + lane) * 16);
#pragma unroll
            for (int p = 0; p < 4; p++)
                lds128(b[p], cB + ((s4 * 8 + wn * 4 + p) * 32 + lane) * 16);
#pragma unroll
            for (int i4 = 0; i4 < 2; i4++)
#pragma unroll
                for (int p = 0; p < 4; p++) {
                    mma16816(acc[i4][2 * p], a[i4], &b[p][0]);
                    mma16816(acc[i4][2 * p + 1], a[i4], &b[p][2]);
                }
        }
        if (elect_one()) mbar_arrive(empty[s]);
    }

    const int r = lane >> 2, c2 = (lane & 3) * 2;
#pragma unroll
    for (int i4 = 0; i4 < 2; i4++) {
        int g0 = gt * 128 + (wm * 2 + i4) * 16 + r;
        float b0 = __ldg(&bih[g0]) + __ldg(&bhh[g0]);
        float b1 = __ldg(&bih[g0 + 8]) + __ldg(&bhh[g0 + 8]);
#pragma unroll
        for (int j = 0; j < 8; j++) {
            int m = mt * 128 + wn * 64 + j * 8 + c2;
            *(float2*)&g_xproj[(size_t)g0 * MTOT + m] =
                make_float2(acc[i4][j][0] + b0, acc[i4][j][1] + b0);
            *(float2*)&g_xproj[(size_t)(g0 + 8) * MTOT + m] =
                make_float2(acc[i4][j][2] + b1, acc[i4][j][3] + b1);
        }
    }
}

// =======================================================================
// Persistent LSTM recurrence: 1-pass fp16, A in REGISTERS (no smem A),
// distance-1 prefetch on h broadcast, Pt reduce + gating, grid barrier.
// =======================================================================
#define P_SMEM (8 * 2112 * 4)     // Pt only: 67584

__device__ __forceinline__ void grid_barrier_128() {
    __syncthreads();
    if (threadIdx.x == 0) {
        __threadfence();
        unsigned g = *((volatile unsigned*)&g_bar_gen);
        if (atomicAdd(&g_bar_count, 1u) == 127u) {
            atomicExch(&g_bar_count, 0u);
            __threadfence();
            atomicAdd(&g_bar_gen, 1u);
        } else {
            while (*((volatile unsigned*)&g_bar_gen) == g) { __nanosleep(64); }
        }
        __threadfence();
    }
    __syncthreads();
}

__global__ __launch_bounds__(256, 1) void lstm_persist(float* __restrict__ out)
{
    extern __shared__ char smc[];
    float* Pt = (float*)smc;                // [8][32][66]
    const int tid = threadIdx.x, wid = tid >> 5, lane = tid & 31;
    const int cta = blockIdx.x;

    // persistent A fragments in registers: warp owns ch {2w, 2w+1}
    uint32_t areg[2][2][4][4];
#pragma unroll
    for (int cc = 0; cc < 2; cc++)
#pragma unroll
        for (int mt2 = 0; mt2 < 2; mt2++)
#pragma unroll
            for (int s = 0; s < 4; s++) {
                const uint4 v = __ldg((const uint4*)(
                    g_Ahh + (size_t)cta * 32768 +
                    ((((wid * 2 + cc) * 2 + mt2) * 4 + s) * 32 + lane) * 8));
                areg[cc][mt2][s][0] = v.x; areg[cc][mt2][s][1] = v.y;
                areg[cc][mt2][s][2] = v.z; areg[cc][mt2][s][3] = v.w;
            }

    const int r = lane >> 2, c2 = (lane & 3) * 2;
    const int gb = tid & 63;
    const int gu = tid >> 6;
    float cst[2] = {0.f, 0.f};
    int par = 0;

    for (int t = 0; t < SEQ; t++) {
        float acc[2][8][4];
#pragma unroll
        for (int i = 0; i < 2; i++)
#pragma unroll
            for (int j = 0; j < 8; j++)
#pragma unroll
                for (int q = 0; q < 4; q++) acc[i][j][q] = 0.f;

        // 8 groups: g = cc*4 + n8p; distance-1 prefetch
        uint4 va[4], vb[4];
        {
            const char* base = (const char*)g_hb + ((size_t)(par * 16 + wid * 2)) * 8192;
#pragma unroll
            for (int s = 0; s < 4; s++)
                va[s] = __ldcg((const uint4*)(base + ((s * 4 + 0) * 32 + lane) * 16));
        }
#pragma unroll
        for (int g = 0; g < 8; g++) {
            uint4* cur = (g & 1) ? vb : va;
            uint4* nxt = (g & 1) ? va : vb;
            if (g < 7) {
                const int gn = g + 1;
                const char* base = (const char*)g_hb +
                    ((size_t)(par * 16 + wid * 2 + (gn >> 2))) * 8192;
                const int np = gn & 3;
#pragma unroll
                for (int s = 0; s < 4; s++)
                    nxt[s] = __ldcg((const uint4*)(base + ((s * 4 + np) * 32 + lane) * 16));
            }
            const int cc = g >> 2, n8p = g & 3;
#pragma unroll
            for (int mt2 = 0; mt2 < 2; mt2++)
#pragma unroll
                for (int s = 0; s < 4; s++) {
                    mma16816(acc[mt2][2 * n8p], areg[cc][mt2][s], &cur[s].x);
                    mma16816(acc[mt2][2 * n8p + 1], areg[cc][mt2][s], &cur[s].z);
                }
        }

#pragma unroll
        for (int mt2 = 0; mt2 < 2; mt2++)
#pragma unroll
            for (int n8 = 0; n8 < 8; n8++) {
                *(float2*)&Pt[wid * 2112 + (mt2 * 16 + r) * 66 + n8 * 8 + c2] =
                    make_float2(acc[mt2][n8][0], acc[mt2][n8][1]);
                *(float2*)&Pt[wid * 2112 + (mt2 * 16 + r + 8) * 66 + n8 * 8 + c2] =
                    make_float2(acc[mt2][n8][2], acc[mt2][n8][3]);
            }
        __syncthreads();

        const int parout = par ^ 1;
#pragma unroll
        for (int p2 = 0; p2 < 2; p2++) {
            const int u = gu * 2 + p2;
            const int jg = cta * 8 + u;
            float gate[4];
#pragma unroll
            for (int gi = 0; gi < 4; gi++) {
                const int m = gi * 8 + u;
                float v = 0.f;
#pragma unroll
                for (int w = 0; w < 8; w++) v += Pt[w * 2112 + m * 66 + gb];
                gate[gi] = v + __ldg(&g_xproj[(size_t)(gi * 1024 + jg) * MTOT + t * 64 + gb]);
            }
            float ig = 1.f / (1.f + __expf(-gate[0]));
            float fg = 1.f / (1.f + __expf(-gate[1]));
            float gtv = tanhf(gate[2]);
            float og = 1.f / (1.f + __expf(-gate[3]));
            float cn = fg * cst[p2] + ig * gtv;
            cst[p2] = cn;
            float hn = og * tanhf(cn);
            const int k = jg;
            const int ch = k >> 6, s4 = (k >> 4) & 3;
            const int n8p = gb >> 4, q = (gb >> 3) & 1;
            const int bl2 = (gb & 7) * 4 + ((k >> 1) & 3);
            const int sl = (k & 1) + 2 * ((k >> 3) & 1);
            const int elem = ((s4 * 4 + n8p) * 32 + bl2) * 8 + q * 4 + sl;
            g_hb[((size_t)(parout * 16 + ch)) * 4096 + elem] = __float2half(hn);
            if (t == SEQ - 1) out[gb * HID + jg] = hn;
        }

        grid_barrier_128();
        par ^= 1;
    }
}

// =======================================================================
extern "C" void kernel_launch(void* const* d_in, const int* in_sizes, int n_in,
                              void* d_out, int out_size)
{
    const float* x   = (const float*)d_in[0];
    const float* Wih = (const float*)d_in[1];
    const float* Whh = (const float*)d_in[2];
    const float* bih = (const float*)d_in[3];
    const float* bhh = (const float*)d_in[4];
    float* out = (float*)d_out;
    (void)in_sizes; (void)n_in; (void)out_size;

    cudaFuncSetAttribute(xproj_tc, cudaFuncAttributeMaxDynamicSharedMemorySize, X_SMEM);
    cudaFuncSetAttribute(lstm_persist, cudaFuncAttributeMaxDynamicSharedMemorySize, P_SMEM);

    prep_all<<<98816, 256>>>(Wih, Whh, x);

    dim3 gx(32, 128);
    xproj_tc<<<gx, 288, X_SMEM>>>(bih, bhh);

    lstm_persist<<<128, 256, P_SMEM>>>(out);
}